// round 9
// baseline (speedup 1.0000x reference)
#include <cuda_runtime.h>
#include <cub/cub.cuh>
#include <cstdint>

#define NIMG 8
#define ATOT 65472
#define NA (NIMG*ATOT)
#define KC 6960
#define NKC (NIMG*KC)
#define NSEG 40
#define SEGCAP 2048
#define POST 2000
#define AMB_CAP 65536
#define NBIN 32768
#define SELCAP 71680

// ---------------- static device scratch (no runtime allocation) ----------------
__device__ unsigned           g_hist[NSEG*NBIN];         // 5.2 MB
__device__ int                g_segB[NSEG];
__device__ unsigned           g_selcnt[NSEG];
__device__ unsigned           g_seloff[NSEG];
__device__ unsigned           g_selcur[NSEG];
__device__ unsigned long long g_ska[SELCAP], g_skb[SELCAP];
__device__ unsigned long long g_k2a[NKC], g_k2b[NKC];
__device__ unsigned           g_v2a[NKC], g_v2b[NKC];
__device__ float4             g_cbox[NKC];
__device__ float              g_score[NKC];
__device__ unsigned char      g_valid[NKC];
__device__ unsigned           g_imgmax[NIMG];            // float bits (coords >= 0)
__device__ unsigned           g_seglist[NSEG*SEGCAP];    // rank -> sorted pos q
__device__ float4             g_segbox[NSEG*SEGCAP];     // offset boxes, rank order
__device__ float              g_segarea[NSEG*SEGCAP];
__device__ unsigned long long g_seginval[NSEG*32];
__device__ unsigned long long g_mask[(size_t)NSEG*SEGCAP*32];  // ~21 MB suppression bitmask
__device__ unsigned char      g_keepq[NKC];
__device__ unsigned           g_ambcnt;
__device__ unsigned           g_amb[AMB_CAP];
__device__ unsigned char      g_cubtmp[64u<<20];

// ---------------- helpers ----------------
__device__ __forceinline__ int lvl_of_anchor(int a){
    return (a<49152)?0:(a<61440)?1:(a<64512)?2:(a<65280)?3:4;
}
__device__ __forceinline__ int lvl_of_p(int p){
    return (p<2000)?0:(p<4000)?1:(p<6000)?2:(p<6768)?3:4;
}
__device__ __forceinline__ int loff_of(int l){
    return (l==0)?0:(l==1)?49152:(l==2)?61440:(l==3)?64512:65280;
}
__device__ __forceinline__ int nlvl_of(int l){
    return (l==0)?49152:(l==1)?12288:(l==2)?3072:(l==3)?768:192;
}
__device__ __forceinline__ int coff_of(int l){
    return (l==0)?0:(l==1)?2000:(l==2)?4000:(l==3)?6000:6768;
}
__device__ __forceinline__ int segk_of(int l){
    return (l<3)?2000:(l==3)?768:192;
}
// ascending-orderable uint for float
__device__ __forceinline__ unsigned fordera(float f){
    unsigned b = __float_as_uint(f);
    return (b & 0x80000000u) ? ~b : (b | 0x80000000u);
}

// XLA logistic: 0.5 + 0.5*tanh(0.5x), tanh = EmitFastTanh rational (Eigen coeffs).
__device__ __forceinline__ float sigmoid_ref(float x){
    float t  = __fmul_rn(0.5f, x);
    float r;
    if (fabsf(t) < 0.0004f) {
        r = t;
    } else {
        float tc = fmaxf(-9.0f, fminf(9.0f, t));
        float s  = __fmul_rn(tc, tc);
        float p  = __fmaf_rn(s, -2.76076847742355e-16f, 2.00018790482477e-13f);
        p = __fmaf_rn(p, s, -8.60467152213735e-11f);
        p = __fmaf_rn(p, s,  5.12229709037114e-08f);
        p = __fmaf_rn(p, s,  1.48572235717979e-05f);
        p = __fmaf_rn(p, s,  6.37261928875436e-04f);
        p = __fmaf_rn(p, s,  4.89352455891786e-03f);
        p = __fmul_rn(p, tc);
        float q = __fmaf_rn(s, 1.19825839466702e-06f, 1.18534705686654e-04f);
        q = __fmaf_rn(q, s, 2.26843463243900e-03f);
        q = __fmaf_rn(q, s, 4.89352518554385e-03f);
        r = __fdiv_rn(p, q);
    }
    return __fmaf_rn(0.5f, r, 0.5f);
}

// Exact predicate: RN(a/u) > 0.7f  <=>  a/u >= m,  m = 0.7f + 2^-25 = 23488103*2^-25.
__device__ __forceinline__ bool exact_pred(float a, float u){
    if (!(a > 0.f) || !(u > 0.f)) return false;
    unsigned ia = __float_as_uint(a), iu = __float_as_uint(u);
    int d = (int)(ia >> 23) - (int)(iu >> 23);
    if (d > 0)  return true;
    if (d < -1) return false;
    unsigned long long Ma = (ia & 0x7FFFFFu) | 0x800000u;
    unsigned long long Mu = (iu & 0x7FFFFFu) | 0x800000u;
    return (Ma << (d + 25)) >= 23488103ull * Mu;
}

// ---------------- kernels ----------------
__global__ void k_zero(){
    int t = blockIdx.x*blockDim.x + threadIdx.x;
    if (t < NIMG)    g_imgmax[t]   = 0u;
    if (t < NSEG*32) g_seginval[t] = 0ull;
    if (t < NSEG)    g_selcur[t]   = 0u;
    if (t == 0)      g_ambcnt = 0u;
    for (int s = t; s < SELCAP; s += gridDim.x*blockDim.x)
        g_ska[s] = ~0ull;
}

// per-segment 32768-bin histogram of the 15-bit prefix of the descending key
__global__ void __launch_bounds__(1024) k_hist(const float* __restrict__ obj){
    int seg = blockIdx.x, i = seg/5, l = seg%5;
    extern __shared__ unsigned sh[];
    for (int b = threadIdx.x; b < NBIN; b += 1024) sh[b] = 0u;
    __syncthreads();
    int n = nlvl_of(l);
    const float* base = obj + (size_t)i*ATOT + loff_of(l);
    for (int t = threadIdx.x; t < n; t += 1024){
        unsigned d = ~fordera(base[t]);
        atomicAdd(&sh[d >> 17], 1u);
    }
    __syncthreads();
    for (int b = threadIdx.x; b < NBIN; b += 1024)
        g_hist[seg*NBIN + b] = sh[b];
}

// find threshold bucket B (first bucket where cumulative >= k) and selected count
__global__ void __launch_bounds__(1024) k_thresh(){
    int seg = blockIdx.x, l = seg%5;
    int k = segk_of(l);
    typedef cub::BlockScan<int, 1024> BS;
    __shared__ typename BS::TempStorage ts;
    int t = threadIdx.x;
    int b0 = t*32, s = 0;
    for (int j = 0; j < 32; j++) s += (int)g_hist[seg*NBIN + b0 + j];
    int ex;
    BS(ts).ExclusiveSum(s, ex);
    if (ex < k && k <= ex + s){
        int c = ex, B = b0;
        for (int j = 0; j < 32; j++){
            c += (int)g_hist[seg*NBIN + b0 + j];
            if (c >= k){ B = b0 + j; break; }
        }
        g_segB[seg] = B;
        g_selcnt[seg] = (unsigned)c;
    }
}

__global__ void k_offs(){
    if (threadIdx.x == 0){
        unsigned acc = 0;
        for (int s = 0; s < NSEG; s++){ g_seloff[s] = acc; acc += g_selcnt[s]; }
    }
}

// compact qualifying anchors; key = seg(6)|desckey(32)|anchor(16), 54 bits
__global__ void k_select(const float* __restrict__ obj){
    int idx = blockIdx.x*blockDim.x + threadIdx.x;
    if (idx >= NA) return;
    int i = idx / ATOT, a = idx % ATOT;
    int l = lvl_of_anchor(a);
    int seg = i*5 + l;
    unsigned d = ~fordera(obj[idx]);
    if ((int)(d >> 17) <= g_segB[seg]){
        unsigned slot = g_seloff[seg] + atomicAdd(&g_selcur[seg], 1u);
        if (slot < SELCAP)
            g_ska[slot] = ((unsigned long long)seg << 48) |
                          ((unsigned long long)d << 16) | (unsigned long long)a;
    }
}

__global__ void k_cand(const float* __restrict__ props){
    int idx = blockIdx.x*blockDim.x + threadIdx.x;
    if (idx >= NKC) return;
    int i = idx / KC, p = idx % KC;
    int l = lvl_of_p(p);
    int r = p - coff_of(l);
    int seg = i*5 + l;
    unsigned long long key = g_skb[g_seloff[seg] + r];
    int a = (int)(key & 0xFFFFull);
    unsigned f = ~(unsigned)(key >> 16);           // fordera bits
    unsigned ob = (f & 0x80000000u) ? (f & 0x7FFFFFFFu) : ~f;
    float o = __uint_as_float(ob);
    int gi  = i*ATOT + a;
    float4 b = *(const float4*)(props + (size_t)gi*4);
    float x1 = fminf(fmaxf(b.x, 0.f), 512.f);
    float y1 = fminf(fmaxf(b.y, 0.f), 512.f);
    float x2 = fminf(fmaxf(b.z, 0.f), 512.f);
    float y2 = fminf(fmaxf(b.w, 0.f), 512.f);
    float sc = sigmoid_ref(o);
    float ws = __fsub_rn(x2, x1), hs = __fsub_rn(y2, y1);
    unsigned char v = (ws >= 0.001f) && (hs >= 0.001f) && (sc >= 0.0f);
    g_cbox[idx]  = make_float4(x1, y1, x2, y2);
    g_score[idx] = sc;
    g_valid[idx] = v;
    float mx = fmaxf(fmaxf(x1, y1), fmaxf(x2, y2));
    atomicMax(&g_imgmax[i], __float_as_uint(mx));
}

__global__ void k_keys2(){
    int idx = blockIdx.x*blockDim.x + threadIdx.x;
    if (idx >= NKC) return;
    int i = idx / KC, p = idx % KC;
    float f = g_valid[idx] ? g_score[idx] : -INFINITY;
    unsigned d = ~fordera(f);                 // descending score; -inf last
    g_k2a[idx] = ((unsigned long long)i << 45) |
                 ((unsigned long long)d << 13) | (unsigned long long)p;
    g_v2a[idx] = (unsigned)p;
}

__global__ void __launch_bounds__(512) k_rank(){
    int i = blockIdx.x, t = threadIdx.x;
    typedef cub::BlockScan<unsigned long long, 512> BS;
    __shared__ typename BS::TempStorage ts;
    unsigned long long items[14], ex[14];
    signed char lv[14];
#pragma unroll
    for (int j = 0; j < 14; j++){
        int q = t*14 + j;
        if (q < KC){
            int p = (int)g_v2b[i*KC + q];
            int l = lvl_of_p(p);
            lv[j] = (signed char)l;
            items[j] = 1ull << (12*l);
        } else { lv[j] = -1; items[j] = 0ull; }
    }
    BS(ts).ExclusiveSum(items, ex);
#pragma unroll
    for (int j = 0; j < 14; j++){
        if (lv[j] >= 0){
            int l = (int)lv[j];
            int rank = (int)((ex[j] >> (12*l)) & 0xFFFull);
            g_seglist[(i*5 + l)*SEGCAP + rank] = (unsigned)(t*14 + j);
        }
    }
}

__global__ void k_pack(){
    int u = blockIdx.x*blockDim.x + threadIdx.x;   // seg*SEGCAP + rank
    if (u >= NSEG*SEGCAP) return;
    int seg = u >> 11, r = u & 2047;
    int l = seg % 5, i = seg / 5;
    int m = segk_of(l);
    if (r < m){
        int q = (int)g_seglist[u];
        int p = (int)g_v2b[i*KC + q];
        int cand = i*KC + p;
        float4 b = g_cbox[cand];
        float mp1 = __fadd_rn(__uint_as_float(g_imgmax[i]), 1.0f);
        float off = __fmul_rn((float)l, mp1);
        float4 ob = make_float4(__fadd_rn(b.x, off), __fadd_rn(b.y, off),
                                __fadd_rn(b.z, off), __fadd_rn(b.w, off));
        g_segbox[u]  = ob;
        g_segarea[u] = __fmul_rn(__fsub_rn(ob.z, ob.x), __fsub_rn(ob.w, ob.y));
        if (!g_valid[cand])
            atomicOr(&g_seginval[seg*32 + (r >> 6)], 1ull << (r & 63));
    } else {
        atomicOr(&g_seginval[seg*32 + (r >> 6)], 1ull << (r & 63));
    }
}

// IoU mask: warp = (rowBlk, word); lanes = 32 consecutive rows; 4 rows/thread.
__global__ void __launch_bounds__(256) k_iou(){
    int seg = blockIdx.y;
    int m = segk_of(seg % 5);
    int gw = blockIdx.x*8 + (threadIdx.x >> 5);
    int lane = threadIdx.x & 31;
    int w = gw & 31;
    int rowBlk = gw >> 5;
    int row0 = rowBlk*128;
    if (row0 >= m) return;
    size_t base = (size_t)seg * SEGCAP;
    int j0 = w * 64;

    int rows[4];
#pragma unroll
    for (int k = 0; k < 4; k++) rows[k] = row0 + k*32 + lane;

    unsigned long long bits[4] = {0,0,0,0}, amb[4] = {0,0,0,0};

    if (j0 + 63 > row0){
        float4 A[4]; float aA[4];
#pragma unroll
        for (int k = 0; k < 4; k++){
            A[k]  = g_segbox[base + rows[k]];
            aA[k] = g_segarea[base + rows[k]];
        }
        int jend = min(j0 + 64, m);
        for (int j = j0; j < jend; j++){
            float4 B = __ldg(&g_segbox[base + j]);
            float aB = __ldg(&g_segarea[base + j]);
            unsigned long long bm = 1ull << (j - j0);
#pragma unroll
            for (int k = 0; k < 4; k++){
                float ltx = fmaxf(A[k].x, B.x), lty = fmaxf(A[k].y, B.y);
                float rbx = fminf(A[k].z, B.z), rby = fminf(A[k].w, B.w);
                float ww = fmaxf(__fsub_rn(rbx, ltx), 0.f);
                float hh = fmaxf(__fsub_rn(rby, lty), 0.f);
                float inter = __fmul_rn(ww, hh);
                float s = __fadd_rn(aA[k], aB);
                float u = __fsub_rn(s, inter);
                float t = __fmaf_rn(0.7f, u, -inter);
                float tau = __fmul_rn(u, 2.384185791015625e-7f);  // u * 2^-22
                if (t < -tau)        bits[k] |= bm;
                if (fabsf(t) <= tau) amb[k]  |= bm;
            }
        }
    }
#pragma unroll
    for (int k = 0; k < 4; k++){
        int cnt = rows[k] - j0 + 1;
        unsigned long long lowm = (cnt <= 0) ? 0ull :
                                  (cnt >= 64) ? ~0ull : ((1ull << cnt) - 1ull);
        bits[k] &= ~lowm;
        amb[k]  &= ~lowm;
        g_mask[(base + rows[k])*32 + w] = bits[k];
        unsigned long long am = amb[k];
        while (am){
            int b = __ffsll((long long)am) - 1;
            am &= am - 1ull;
            unsigned slot = atomicAdd(&g_ambcnt, 1u);
            if (slot < AMB_CAP)
                g_amb[slot] = ((unsigned)seg << 22) | ((unsigned)rows[k] << 11)
                            | (unsigned)(j0 + b);
        }
    }
}

__global__ void k_fix(){
    unsigned n = g_ambcnt; if (n > AMB_CAP) n = AMB_CAP;
    for (unsigned t = blockIdx.x*blockDim.x + threadIdx.x; t < n;
         t += gridDim.x*blockDim.x){
        unsigned e = g_amb[t];
        int seg = (int)(e >> 22), row = (int)((e >> 11) & 0x7FFu), j = (int)(e & 0x7FFu);
        size_t base = (size_t)seg * SEGCAP;
        float4 A = g_segbox[base + row]; float aA = g_segarea[base + row];
        float4 B = g_segbox[base + j];   float aB = g_segarea[base + j];
        float ltx = fmaxf(A.x, B.x), lty = fmaxf(A.y, B.y);
        float rbx = fminf(A.z, B.z), rby = fminf(A.w, B.w);
        float ww = fmaxf(__fsub_rn(rbx, ltx), 0.f);
        float hh = fmaxf(__fsub_rn(rby, lty), 0.f);
        float inter = __fmul_rn(ww, hh);
        float u = __fsub_rn(__fadd_rn(aA, aB), inter);
        float tt = __fmaf_rn(0.7f, u, -inter);
        float tau = __fmul_rn(u, 2.384185791015625e-7f);
        bool guess = (tt < -tau);
        bool ex = exact_pred(inter, u);
        if (ex != guess)
            atomicXor(&g_mask[(base + row)*32 + (j >> 6)], 1ull << (j & 63));
    }
}

__global__ void k_sweep(){
    int seg = blockIdx.x, lane = threadIdx.x;
    int l = seg % 5, i = seg / 5, m = segk_of(l);
    size_t mb = (size_t)seg * SEGCAP * 32;
    unsigned long long removed = g_seginval[seg*32 + lane];
    unsigned long long buf[8];
#pragma unroll
    for (int k = 0; k < 8; k++)
        buf[k] = (k < m) ? g_mask[mb + (size_t)k*32 + lane] : 0ull;
    for (int basei = 0; basei < m; basei += 8){
        unsigned long long nbuf[8];
#pragma unroll
        for (int k = 0; k < 8; k++){
            int rr = basei + 8 + k;
            nbuf[k] = (rr < m) ? g_mask[mb + (size_t)rr*32 + lane] : 0ull;
        }
#pragma unroll
        for (int k = 0; k < 8; k++){
            int ii = basei + k;
            if (ii >= m) break;
            unsigned long long rw = __shfl_sync(0xFFFFFFFFu, removed, ii >> 6);
            if (!((rw >> (ii & 63)) & 1ull)) removed |= buf[k];
        }
#pragma unroll
        for (int k = 0; k < 8; k++) buf[k] = nbuf[k];
    }
    for (int b = 0; b < 64; b++){
        int r = lane*64 + b;
        if (r < m){
            unsigned q = g_seglist[seg*SEGCAP + r];
            g_keepq[i*KC + q] = (unsigned char)(((removed >> b) & 1ull) ^ 1ull);
        }
    }
}

__global__ void __launch_bounds__(512) k_out(float* __restrict__ out){
    int i = blockIdx.x, t = threadIdx.x;
    typedef cub::BlockScan<int, 512> BS;
    __shared__ typename BS::TempStorage ts;
    __shared__ int s_tot;
    int kp[14], ex[14];
#pragma unroll
    for (int j = 0; j < 14; j++){
        int q = t*14 + j;
        kp[j] = (q < KC) ? (int)g_keepq[i*KC + q] : 0;
    }
    int agg;
    BS(ts).ExclusiveSum(kp, ex, agg);
    if (t == 0) s_tot = agg;
    __syncthreads();
    float* ob = out + (size_t)i*POST*4;
    float* os = out + (size_t)NIMG*POST*4 + (size_t)i*POST;
#pragma unroll
    for (int j = 0; j < 14; j++){
        int q = t*14 + j;
        if (q < KC && kp[j] && ex[j] < POST){
            int p = (int)g_v2b[i*KC + q];
            int cand = i*KC + p;
            *(float4*)(ob + ex[j]*4) = g_cbox[cand];
            os[ex[j]] = g_score[cand];
        }
    }
    int T = min(s_tot, POST);
    for (int s = T + t; s < POST; s += 512){
        *(float4*)(ob + s*4) = make_float4(0.f, 0.f, 0.f, 0.f);
        os[s] = 0.f;
    }
}

// ---------------- launch ----------------
extern "C" void kernel_launch(void* const* d_in, const int* in_sizes, int n_in,
                              void* d_out, int out_size){
    const float* props = (const float*)d_in[0];
    const float* obj   = (const float*)d_in[1];
    float* out = (float*)d_out;

    void *pska, *pskb, *pk2a, *pk2b, *pv2a, *pv2b, *ptmp;
    cudaGetSymbolAddress(&pska, g_ska); cudaGetSymbolAddress(&pskb, g_skb);
    cudaGetSymbolAddress(&pk2a, g_k2a); cudaGetSymbolAddress(&pk2b, g_k2b);
    cudaGetSymbolAddress(&pv2a, g_v2a); cudaGetSymbolAddress(&pv2b, g_v2b);
    cudaGetSymbolAddress(&ptmp, g_cubtmp);

    cudaFuncSetAttribute(k_hist, cudaFuncAttributeMaxDynamicSharedMemorySize,
                         NBIN*sizeof(unsigned));

    k_zero<<<70, 1024>>>();
    k_hist<<<NSEG, 1024, NBIN*sizeof(unsigned)>>>(obj);
    k_thresh<<<NSEG, 1024>>>();
    k_offs<<<1, 32>>>();
    k_select<<<(NA + 255)/256, 256>>>(obj);

    size_t tb = sizeof(g_cubtmp);
    cub::DeviceRadixSort::SortKeys(ptmp, tb,
        (const unsigned long long*)pska, (unsigned long long*)pskb,
        SELCAP, 0, 54);

    k_cand<<<(NKC + 255)/256, 256>>>(props);
    k_keys2<<<(NKC + 255)/256, 256>>>();

    size_t tb2 = sizeof(g_cubtmp);
    cub::DeviceRadixSort::SortPairs(ptmp, tb2,
        (const unsigned long long*)pk2a, (unsigned long long*)pk2b,
        (const unsigned*)pv2a, (unsigned*)pv2b, NKC, 0, 48);

    k_rank<<<NIMG, 512>>>();
    k_pack<<<(NSEG*SEGCAP + 255)/256, 256>>>();
    dim3 giou(64, NSEG);
    k_iou<<<giou, 256>>>();
    k_fix<<<4, 256>>>();
    k_sweep<<<NSEG, 32>>>();
    k_out<<<NIMG, 512>>>(out);
}

// round 11
// speedup vs baseline: 1.1668x; 1.1668x over previous
#include <cuda_runtime.h>
#include <cub/cub.cuh>
#include <cstdint>

#define NIMG 8
#define ATOT 65472
#define NA (NIMG*ATOT)
#define KC 6960
#define NKC (NIMG*KC)
#define NSEG 40
#define SEGCAP 2048
#define POST 2000
#define AMB_CAP 65536

// ---------------- static device scratch (no runtime allocation) ----------------
__device__ unsigned long long g_k1a[NA], g_k1b[NA];
__device__ unsigned           g_v1a[NA], g_v1b[NA];
__device__ unsigned long long g_k2a[NKC], g_k2b[NKC];
__device__ unsigned           g_v2a[NKC], g_v2b[NKC];
__device__ float4             g_cbox[NKC];
__device__ float              g_score[NKC];
__device__ unsigned char      g_valid[NKC];
__device__ unsigned           g_imgmax[NIMG];            // float bits (coords >= 0)
__device__ unsigned           g_seglist[NSEG*SEGCAP];    // rank -> sorted pos q
__device__ float4             g_segbox[NSEG*SEGCAP];     // offset boxes, rank order
__device__ float              g_segarea[NSEG*SEGCAP];
__device__ unsigned long long g_seginval[NSEG*32];
__device__ unsigned long long g_mask[(size_t)NSEG*SEGCAP*32];  // ~21 MB suppression bitmask
__device__ unsigned char      g_keepq[NKC];
__device__ unsigned           g_ambcnt;
__device__ unsigned           g_amb[AMB_CAP];
__device__ unsigned char      g_cubtmp[64u<<20];

// ---------------- helpers ----------------
__device__ __forceinline__ int lvl_of_anchor(int a){
    return (a<49152)?0:(a<61440)?1:(a<64512)?2:(a<65280)?3:4;
}
__device__ __forceinline__ int lvl_of_p(int p){
    return (p<2000)?0:(p<4000)?1:(p<6000)?2:(p<6768)?3:4;
}
__device__ __forceinline__ int loff_of(int l){
    return (l==0)?0:(l==1)?49152:(l==2)?61440:(l==3)?64512:65280;
}
__device__ __forceinline__ int coff_of(int l){
    return (l==0)?0:(l==1)?2000:(l==2)?4000:(l==3)?6000:6768;
}
__device__ __forceinline__ int segk_of(int l){
    return (l<3)?2000:(l==3)?768:192;
}
// ascending-orderable uint for float
__device__ __forceinline__ unsigned fordera(float f){
    unsigned b = __float_as_uint(f);
    return (b & 0x80000000u) ? ~b : (b | 0x80000000u);
}

// XLA logistic: 0.5 + 0.5*tanh(0.5x), tanh = EmitFastTanh rational (Eigen coeffs).
__device__ __forceinline__ float sigmoid_ref(float x){
    float t  = __fmul_rn(0.5f, x);
    float r;
    if (fabsf(t) < 0.0004f) {
        r = t;
    } else {
        float tc = fmaxf(-9.0f, fminf(9.0f, t));
        float s  = __fmul_rn(tc, tc);
        float p  = __fmaf_rn(s, -2.76076847742355e-16f, 2.00018790482477e-13f);
        p = __fmaf_rn(p, s, -8.60467152213735e-11f);
        p = __fmaf_rn(p, s,  5.12229709037114e-08f);
        p = __fmaf_rn(p, s,  1.48572235717979e-05f);
        p = __fmaf_rn(p, s,  6.37261928875436e-04f);
        p = __fmaf_rn(p, s,  4.89352455891786e-03f);
        p = __fmul_rn(p, tc);
        float q = __fmaf_rn(s, 1.19825839466702e-06f, 1.18534705686654e-04f);
        q = __fmaf_rn(q, s, 2.26843463243900e-03f);
        q = __fmaf_rn(q, s, 4.89352518554385e-03f);
        r = __fdiv_rn(p, q);
    }
    return __fmaf_rn(0.5f, r, 0.5f);
}

// Exact predicate: RN(a/u) > 0.7f  <=>  a/u >= m,  m = 0.7f + 2^-25 = 23488103*2^-25.
__device__ __forceinline__ bool exact_pred(float a, float u){
    if (!(a > 0.f) || !(u > 0.f)) return false;
    unsigned ia = __float_as_uint(a), iu = __float_as_uint(u);
    int d = (int)(ia >> 23) - (int)(iu >> 23);
    if (d > 0)  return true;
    if (d < -1) return false;
    unsigned long long Ma = (ia & 0x7FFFFFu) | 0x800000u;
    unsigned long long Mu = (iu & 0x7FFFFFu) | 0x800000u;
    return (Ma << (d + 25)) >= 23488103ull * Mu;
}

// ---------------- kernels ----------------
__global__ void k_zero(){
    int t = blockIdx.x*blockDim.x + threadIdx.x;
    if (t < NIMG)    g_imgmax[t]   = 0u;
    if (t < NSEG*32) g_seginval[t] = 0ull;
    if (t == 0)      g_ambcnt = 0u;
}

__global__ void k_keys1(const float* __restrict__ obj){
    int idx = blockIdx.x*blockDim.x + threadIdx.x;
    if (idx >= NA) return;
    int i = idx / ATOT, a = idx % ATOT;
    int l = lvl_of_anchor(a);
    unsigned d = ~fordera(obj[idx]);          // descending objectness
    g_k1a[idx] = ((unsigned long long)(i*5+l) << 32) | d;
    g_v1a[idx] = (unsigned)a;
}

__global__ void k_cand(const float* __restrict__ props, const float* __restrict__ obj){
    int idx = blockIdx.x*blockDim.x + threadIdx.x;
    if (idx >= NKC) return;
    int i = idx / KC, p = idx % KC;
    int l = lvl_of_p(p);
    int r = p - coff_of(l);
    int srt = i*ATOT + loff_of(l) + r;
    int a   = (int)g_v1b[srt];
    int gi  = i*ATOT + a;
    float o = obj[gi];
    float4 b = *(const float4*)(props + (size_t)gi*4);
    float x1 = fminf(fmaxf(b.x, 0.f), 512.f);
    float y1 = fminf(fmaxf(b.y, 0.f), 512.f);
    float x2 = fminf(fmaxf(b.z, 0.f), 512.f);
    float y2 = fminf(fmaxf(b.w, 0.f), 512.f);
    float sc = sigmoid_ref(o);
    float ws = __fsub_rn(x2, x1), hs = __fsub_rn(y2, y1);
    unsigned char v = (ws >= 0.001f) && (hs >= 0.001f) && (sc >= 0.0f);
    g_cbox[idx]  = make_float4(x1, y1, x2, y2);
    g_score[idx] = sc;
    g_valid[idx] = v;
    float mx = fmaxf(fmaxf(x1, y1), fmaxf(x2, y2));
    atomicMax(&g_imgmax[i], __float_as_uint(mx));
}

__global__ void k_keys2(){
    int idx = blockIdx.x*blockDim.x + threadIdx.x;
    if (idx >= NKC) return;
    int i = idx / KC, p = idx % KC;
    float f = g_valid[idx] ? g_score[idx] : -INFINITY;
    unsigned d = ~fordera(f);                 // descending score; -inf last
    g_k2a[idx] = ((unsigned long long)i << 45) |
                 ((unsigned long long)d << 13) | (unsigned long long)p;
    g_v2a[idx] = (unsigned)p;
}

__global__ void __launch_bounds__(512) k_rank(){
    int i = blockIdx.x, t = threadIdx.x;
    typedef cub::BlockScan<unsigned long long, 512> BS;
    __shared__ typename BS::TempStorage ts;
    unsigned long long items[14], ex[14];
    signed char lv[14];
#pragma unroll
    for (int j = 0; j < 14; j++){
        int q = t*14 + j;
        if (q < KC){
            int p = (int)g_v2b[i*KC + q];
            int l = lvl_of_p(p);
            lv[j] = (signed char)l;
            items[j] = 1ull << (12*l);
        } else { lv[j] = -1; items[j] = 0ull; }
    }
    BS(ts).ExclusiveSum(items, ex);
#pragma unroll
    for (int j = 0; j < 14; j++){
        if (lv[j] >= 0){
            int l = (int)lv[j];
            int rank = (int)((ex[j] >> (12*l)) & 0xFFFull);
            g_seglist[(i*5 + l)*SEGCAP + rank] = (unsigned)(t*14 + j);
        }
    }
}

__global__ void k_pack(){
    int u = blockIdx.x*blockDim.x + threadIdx.x;   // seg*SEGCAP + rank
    if (u >= NSEG*SEGCAP) return;
    int seg = u >> 11, r = u & 2047;
    int l = seg % 5, i = seg / 5;
    int m = segk_of(l);
    if (r < m){
        int q = (int)g_seglist[u];
        int p = (int)g_v2b[i*KC + q];
        int cand = i*KC + p;
        float4 b = g_cbox[cand];
        float mp1 = __fadd_rn(__uint_as_float(g_imgmax[i]), 1.0f);
        float off = __fmul_rn((float)l, mp1);
        float4 ob = make_float4(__fadd_rn(b.x, off), __fadd_rn(b.y, off),
                                __fadd_rn(b.z, off), __fadd_rn(b.w, off));
        g_segbox[u]  = ob;
        g_segarea[u] = __fmul_rn(__fsub_rn(ob.z, ob.x), __fsub_rn(ob.w, ob.y));
        if (!g_valid[cand])
            atomicOr(&g_seginval[seg*32 + (r >> 6)], 1ull << (r & 63));
    } else {
        atomicOr(&g_seginval[seg*32 + (r >> 6)], 1ull << (r & 63));
    }
}

// IoU mask v2: warp = (rowBlk, word); lanes = 32 consecutive rows; 4 rows/thread.
// Phase 1: cheap x&y-overlap bitmask (B broadcast from per-warp smem tile).
// Phase 2: full (bit-identical to R8) test only on overlapping pairs (~6%).
__global__ void __launch_bounds__(256) k_iou(){
    int seg = blockIdx.y;
    int m = segk_of(seg % 5);
    int wid  = threadIdx.x >> 5;
    int gw   = blockIdx.x*8 + wid;
    int lane = threadIdx.x & 31;
    int w = gw & 31;                               // column word
    int rowBlk = gw >> 5;                          // 0..15
    int row0 = rowBlk*128;
    if (row0 >= m) return;                         // warp-uniform
    size_t base = (size_t)seg * SEGCAP;
    int j0 = w * 64;

    __shared__ float4 sB[8][64];
    __shared__ float  sAr[8][64];

    int rows[4];
#pragma unroll
    for (int k = 0; k < 4; k++) rows[k] = row0 + k*32 + lane;

    unsigned long long bits[4] = {0,0,0,0}, amb[4] = {0,0,0,0};

    if (j0 + 63 > row0){
        int jend = min(j0 + 64, m);
        // stage B tile (boxes + areas) into this warp's smem slice
#pragma unroll
        for (int s = 0; s < 2; s++){
            int jj = lane + s*32;
            if (j0 + jj < m){
                sB[wid][jj]  = g_segbox[base + j0 + jj];
                sAr[wid][jj] = g_segarea[base + j0 + jj];
            }
        }
        __syncwarp();

        float4 A[4]; float aA[4];
#pragma unroll
        for (int k = 0; k < 4; k++){
            A[k]  = g_segbox[base + rows[k]];
            aA[k] = g_segarea[base + rows[k]];
        }

        // ---- phase 1: overlap prescreen ----
        unsigned long long xm[4] = {0,0,0,0};
        for (int j = j0; j < jend; j++){
            float4 B = sB[wid][j - j0];
            unsigned long long bm = 1ull << (j - j0);
#pragma unroll
            for (int k = 0; k < 4; k++){
                float ltx = fmaxf(A[k].x, B.x), lty = fmaxf(A[k].y, B.y);
                float rbx = fminf(A[k].z, B.z), rby = fminf(A[k].w, B.w);
                if (rbx > ltx && rby > lty) xm[k] |= bm;
            }
        }
        // clear sub-diagonal before phase 2 (also trims work)
#pragma unroll
        for (int k = 0; k < 4; k++){
            int cnt = rows[k] - j0 + 1;
            unsigned long long lowm = (cnt <= 0) ? 0ull :
                                      (cnt >= 64) ? ~0ull : ((1ull << cnt) - 1ull);
            xm[k] &= ~lowm;
        }

        // ---- phase 2: exact test on surviving pairs only ----
#pragma unroll
        for (int k = 0; k < 4; k++){
            unsigned long long x = xm[k];
            while (x){
                int b = __ffsll((long long)x) - 1;
                x &= x - 1ull;
                float4 B = sB[wid][b];
                float aB = sAr[wid][b];
                float ltx = fmaxf(A[k].x, B.x), lty = fmaxf(A[k].y, B.y);
                float rbx = fminf(A[k].z, B.z), rby = fminf(A[k].w, B.w);
                float ww = fmaxf(__fsub_rn(rbx, ltx), 0.f);
                float hh = fmaxf(__fsub_rn(rby, lty), 0.f);
                float inter = __fmul_rn(ww, hh);
                float s = __fadd_rn(aA[k], aB);
                float u = __fsub_rn(s, inter);
                float t = __fmaf_rn(0.7f, u, -inter);
                float tau = __fmul_rn(u, 2.384185791015625e-7f);  // u * 2^-22
                unsigned long long bm = 1ull << b;
                if (t < -tau)        bits[k] |= bm;
                if (fabsf(t) <= tau) amb[k]  |= bm;
            }
        }
    }
    // store (zeros for skipped tiles / masked regions)
#pragma unroll
    for (int k = 0; k < 4; k++){
        g_mask[(base + rows[k])*32 + w] = bits[k];
        unsigned long long am = amb[k];
        while (am){
            int b = __ffsll((long long)am) - 1;
            am &= am - 1ull;
            unsigned slot = atomicAdd(&g_ambcnt, 1u);
            if (slot < AMB_CAP)
                g_amb[slot] = ((unsigned)seg << 22) | ((unsigned)rows[k] << 11)
                            | (unsigned)(j0 + b);
        }
    }
}

__global__ void k_fix(){
    unsigned n = g_ambcnt; if (n > AMB_CAP) n = AMB_CAP;
    for (unsigned t = blockIdx.x*blockDim.x + threadIdx.x; t < n;
         t += gridDim.x*blockDim.x){
        unsigned e = g_amb[t];
        int seg = (int)(e >> 22), row = (int)((e >> 11) & 0x7FFu), j = (int)(e & 0x7FFu);
        size_t base = (size_t)seg * SEGCAP;
        float4 A = g_segbox[base + row]; float aA = g_segarea[base + row];
        float4 B = g_segbox[base + j];   float aB = g_segarea[base + j];
        float ltx = fmaxf(A.x, B.x), lty = fmaxf(A.y, B.y);
        float rbx = fminf(A.z, B.z), rby = fminf(A.w, B.w);
        float ww = fmaxf(__fsub_rn(rbx, ltx), 0.f);
        float hh = fmaxf(__fsub_rn(rby, lty), 0.f);
        float inter = __fmul_rn(ww, hh);
        float u = __fsub_rn(__fadd_rn(aA, aB), inter);
        float tt = __fmaf_rn(0.7f, u, -inter);
        float tau = __fmul_rn(u, 2.384185791015625e-7f);
        bool guess = (tt < -tau);
        bool ex = exact_pred(inter, u);
        if (ex != guess)
            atomicXor(&g_mask[(base + row)*32 + (j >> 6)], 1ull << (j & 63));
    }
}

__global__ void k_sweep(){
    int seg = blockIdx.x, lane = threadIdx.x;
    int l = seg % 5, i = seg / 5, m = segk_of(l);
    size_t mb = (size_t)seg * SEGCAP * 32;
    unsigned long long removed = g_seginval[seg*32 + lane];
    unsigned long long buf[8];
#pragma unroll
    for (int k = 0; k < 8; k++)
        buf[k] = (k < m) ? g_mask[mb + (size_t)k*32 + lane] : 0ull;
    for (int basei = 0; basei < m; basei += 8){
        unsigned long long nbuf[8];
#pragma unroll
        for (int k = 0; k < 8; k++){
            int rr = basei + 8 + k;
            nbuf[k] = (rr < m) ? g_mask[mb + (size_t)rr*32 + lane] : 0ull;
        }
#pragma unroll
        for (int k = 0; k < 8; k++){
            int ii = basei + k;
            if (ii >= m) break;
            unsigned long long rw = __shfl_sync(0xFFFFFFFFu, removed, ii >> 6);
            if (!((rw >> (ii & 63)) & 1ull)) removed |= buf[k];
        }
#pragma unroll
        for (int k = 0; k < 8; k++) buf[k] = nbuf[k];
    }
    for (int b = 0; b < 64; b++){
        int r = lane*64 + b;
        if (r < m){
            unsigned q = g_seglist[seg*SEGCAP + r];
            g_keepq[i*KC + q] = (unsigned char)(((removed >> b) & 1ull) ^ 1ull);
        }
    }
}

__global__ void __launch_bounds__(512) k_out(float* __restrict__ out){
    int i = blockIdx.x, t = threadIdx.x;
    typedef cub::BlockScan<int, 512> BS;
    __shared__ typename BS::TempStorage ts;
    __shared__ int s_tot;
    int kp[14], ex[14];
#pragma unroll
    for (int j = 0; j < 14; j++){
        int q = t*14 + j;
        kp[j] = (q < KC) ? (int)g_keepq[i*KC + q] : 0;
    }
    int agg;
    BS(ts).ExclusiveSum(kp, ex, agg);
    if (t == 0) s_tot = agg;
    __syncthreads();
    float* ob = out + (size_t)i*POST*4;
    float* os = out + (size_t)NIMG*POST*4 + (size_t)i*POST;
#pragma unroll
    for (int j = 0; j < 14; j++){
        int q = t*14 + j;
        if (q < KC && kp[j] && ex[j] < POST){
            int p = (int)g_v2b[i*KC + q];
            int cand = i*KC + p;
            *(float4*)(ob + ex[j]*4) = g_cbox[cand];
            os[ex[j]] = g_score[cand];
        }
    }
    int T = min(s_tot, POST);
    for (int s = T + t; s < POST; s += 512){
        *(float4*)(ob + s*4) = make_float4(0.f, 0.f, 0.f, 0.f);
        os[s] = 0.f;
    }
}

// ---------------- launch ----------------
extern "C" void kernel_launch(void* const* d_in, const int* in_sizes, int n_in,
                              void* d_out, int out_size){
    const float* props = (const float*)d_in[0];
    const float* obj   = (const float*)d_in[1];
    float* out = (float*)d_out;

    void *pk1a, *pk1b, *pv1a, *pv1b, *pk2a, *pk2b, *pv2a, *pv2b, *ptmp;
    cudaGetSymbolAddress(&pk1a, g_k1a); cudaGetSymbolAddress(&pk1b, g_k1b);
    cudaGetSymbolAddress(&pv1a, g_v1a); cudaGetSymbolAddress(&pv1b, g_v1b);
    cudaGetSymbolAddress(&pk2a, g_k2a); cudaGetSymbolAddress(&pk2b, g_k2b);
    cudaGetSymbolAddress(&pv2a, g_v2a); cudaGetSymbolAddress(&pv2b, g_v2b);
    cudaGetSymbolAddress(&ptmp, g_cubtmp);

    k_zero<<<5, 256>>>();
    k_keys1<<<(NA + 255)/256, 256>>>(obj);

    size_t tb = sizeof(g_cubtmp);
    cub::DeviceRadixSort::SortPairs(ptmp, tb,
        (const unsigned long long*)pk1a, (unsigned long long*)pk1b,
        (const unsigned*)pv1a, (unsigned*)pv1b, NA, 0, 38);

    k_cand<<<(NKC + 255)/256, 256>>>(props, obj);
    k_keys2<<<(NKC + 255)/256, 256>>>();

    size_t tb2 = sizeof(g_cubtmp);
    cub::DeviceRadixSort::SortPairs(ptmp, tb2,
        (const unsigned long long*)pk2a, (unsigned long long*)pk2b,
        (const unsigned*)pv2a, (unsigned*)pv2b, NKC, 0, 48);

    k_rank<<<NIMG, 512>>>();
    k_pack<<<(NSEG*SEGCAP + 255)/256, 256>>>();
    dim3 giou(64, NSEG);
    k_iou<<<giou, 256>>>();
    k_fix<<<4, 256>>>();
    k_sweep<<<NSEG, 32>>>();
    k_out<<<NIMG, 512>>>(out);
}

// round 12
// speedup vs baseline: 1.3788x; 1.1817x over previous
#include <cuda_runtime.h>
#include <cub/cub.cuh>
#include <cstdint>

#define NIMG 8
#define ATOT 65472
#define NA (NIMG*ATOT)
#define KC 6960
#define NKC (NIMG*KC)
#define NSEG 40
#define SEGCAP 2048
#define SELCAP 4096
#define POST 2000
#define AMB_CAP 65536
#define NBIN 32768

// ---------------- static device scratch (no runtime allocation) ----------------
__device__ unsigned           g_selk[NSEG*SELCAP];       // desckeys per segment
__device__ unsigned           g_selv[NSEG*SELCAP];       // absolute anchor ids
__device__ unsigned           g_segsel[NSEG*SEGCAP];     // sorted anchors (top-k order)
__device__ unsigned           g_v2b[NKC];                // per-image sorted p
__device__ float4             g_cbox[NKC];
__device__ float              g_score[NKC];
__device__ unsigned char      g_valid[NKC];
__device__ unsigned           g_imgmax[NIMG];            // float bits (coords >= 0)
__device__ unsigned           g_seglist[NSEG*SEGCAP];    // rank -> sorted pos q
__device__ float4             g_segbox[NSEG*SEGCAP];     // offset boxes, rank order
__device__ float              g_segarea[NSEG*SEGCAP];
__device__ unsigned long long g_seginval[NSEG*32];
__device__ unsigned long long g_mask[(size_t)NSEG*SEGCAP*32];  // ~21 MB suppression bitmask
__device__ unsigned char      g_keepq[NKC];
__device__ unsigned           g_ambcnt;
__device__ unsigned           g_amb[AMB_CAP];

// CUB block primitives (types shared host/device for sizeof)
typedef cub::BlockRadixSort<unsigned, 1024, 4, unsigned> SegSortT;
typedef cub::BlockRadixSort<unsigned, 1024, 7, unsigned> ImgSortT;
typedef cub::BlockScan<unsigned long long, 1024>         ImgScanT;
struct ImgSmemT { union { ImgSortT::TempStorage sort; ImgScanT::TempStorage scan; } u; };

// ---------------- helpers ----------------
__device__ __forceinline__ int lvl_of_p(int p){
    return (p<2000)?0:(p<4000)?1:(p<6000)?2:(p<6768)?3:4;
}
__device__ __forceinline__ int loff_of(int l){
    return (l==0)?0:(l==1)?49152:(l==2)?61440:(l==3)?64512:65280;
}
__device__ __forceinline__ int nlvl_of(int l){
    return (l==0)?49152:(l==1)?12288:(l==2)?3072:(l==3)?768:192;
}
__device__ __forceinline__ int coff_of(int l){
    return (l==0)?0:(l==1)?2000:(l==2)?4000:(l==3)?6000:6768;
}
__device__ __forceinline__ int segk_of(int l){
    return (l<3)?2000:(l==3)?768:192;
}
__device__ __forceinline__ unsigned fordera(float f){
    unsigned b = __float_as_uint(f);
    return (b & 0x80000000u) ? ~b : (b | 0x80000000u);
}

// XLA logistic: 0.5 + 0.5*tanh(0.5x), tanh = EmitFastTanh rational (Eigen coeffs).
__device__ __forceinline__ float sigmoid_ref(float x){
    float t  = __fmul_rn(0.5f, x);
    float r;
    if (fabsf(t) < 0.0004f) {
        r = t;
    } else {
        float tc = fmaxf(-9.0f, fminf(9.0f, t));
        float s  = __fmul_rn(tc, tc);
        float p  = __fmaf_rn(s, -2.76076847742355e-16f, 2.00018790482477e-13f);
        p = __fmaf_rn(p, s, -8.60467152213735e-11f);
        p = __fmaf_rn(p, s,  5.12229709037114e-08f);
        p = __fmaf_rn(p, s,  1.48572235717979e-05f);
        p = __fmaf_rn(p, s,  6.37261928875436e-04f);
        p = __fmaf_rn(p, s,  4.89352455891786e-03f);
        p = __fmul_rn(p, tc);
        float q = __fmaf_rn(s, 1.19825839466702e-06f, 1.18534705686654e-04f);
        q = __fmaf_rn(q, s, 2.26843463243900e-03f);
        q = __fmaf_rn(q, s, 4.89352518554385e-03f);
        r = __fdiv_rn(p, q);
    }
    return __fmaf_rn(0.5f, r, 0.5f);
}

// Exact predicate: RN(a/u) > 0.7f  <=>  a/u >= m,  m = 0.7f + 2^-25 = 23488103*2^-25.
__device__ __forceinline__ bool exact_pred(float a, float u){
    if (!(a > 0.f) || !(u > 0.f)) return false;
    unsigned ia = __float_as_uint(a), iu = __float_as_uint(u);
    int d = (int)(ia >> 23) - (int)(iu >> 23);
    if (d > 0)  return true;
    if (d < -1) return false;
    unsigned long long Ma = (ia & 0x7FFFFFu) | 0x800000u;
    unsigned long long Mu = (iu & 0x7FFFFFu) | 0x800000u;
    return (Ma << (d + 25)) >= 23488103ull * Mu;
}

// ---------------- kernels ----------------
// Per-segment histogram top-k select (replaces keys1 + device sort1) + all inits.
__global__ void __launch_bounds__(1024) k_select(const float* __restrict__ obj){
    int seg = blockIdx.x, i = seg/5, l = seg%5;
    int n = nlvl_of(l), kk = segk_of(l);
    int t = threadIdx.x;
    extern __shared__ unsigned hist[];          // 32768 bins
    typedef cub::BlockScan<int, 1024> BS;
    __shared__ typename BS::TempStorage ts;
    __shared__ int sB, sCnt;

    // global inits (consumers all launch later)
    if (seg == 0){
        if (t < NIMG) g_imgmax[t] = 0u;
        if (t == 0)   g_ambcnt = 0u;
    }
    if (t < 32){                                 // seginval: padding ranks r>=kk start invalid
        int r0 = t*64;
        unsigned long long v = (kk <= r0) ? ~0ull :
                               (kk >= r0+64) ? 0ull : (~0ull << (kk - r0));
        g_seginval[seg*32 + t] = v;
    }
    for (int b = t; b < NBIN; b += 1024) hist[b] = 0u;
    __syncthreads();

    const float* base = obj + (size_t)i*ATOT + loff_of(l);
    for (int s = t; s < n; s += 1024){
        unsigned d = ~fordera(base[s]);
        atomicAdd(&hist[d >> 17], 1u);
    }
    __syncthreads();

    // threshold bucket: first bucket where cumulative >= kk
    {
        int b0 = t*32, s32 = 0;
        for (int j = 0; j < 32; j++) s32 += (int)hist[b0 + j];
        int ex;
        BS(ts).ExclusiveSum(s32, ex);
        if (ex < kk && kk <= ex + s32){
            int c = ex;
            for (int j = 0; j < 32; j++){
                c += (int)hist[b0 + j];
                if (c >= kk){ sB = b0 + j; sCnt = c; break; }
            }
        }
    }
    __syncthreads();
    int B = sB;

    // stable compaction: thread-contiguous chunks preserve anchor-ascending order
    int chunk = (n + 1023) / 1024;
    int lo = t*chunk, hi = min(n, lo + chunk);
    int cnt = 0;
    for (int s = lo; s < hi; s++){
        unsigned d = ~fordera(base[s]);
        if ((int)(d >> 17) <= B) cnt++;
    }
    int off;
    __syncthreads();                             // reuse ts
    BS(ts).ExclusiveSum(cnt, off);
    for (int s = lo; s < hi; s++){
        unsigned d = ~fordera(base[s]);
        if ((int)(d >> 17) <= B){
            g_selk[seg*SELCAP + off] = d;
            g_selv[seg*SELCAP + off] = (unsigned)(loff_of(l) + s);   // absolute anchor
            off++;
        }
    }
    __syncthreads();
    for (int s = sCnt + t; s < SELCAP; s += 1024){   // sentinel pad
        g_selk[seg*SELCAP + s] = 0xFFFFFFFFu;
        g_selv[seg*SELCAP + s] = 0u;
    }
}

// Per-segment stable in-block sort by desckey (ties -> anchor asc from input order).
__global__ void __launch_bounds__(1024) k_segsort(){
    int seg = blockIdx.x, t = threadIdx.x;
    int kk = segk_of(seg % 5);
    extern __shared__ char sm[];
    auto& ts = *reinterpret_cast<SegSortT::TempStorage*>(sm);
    unsigned keys[4], vals[4];
#pragma unroll
    for (int j = 0; j < 4; j++){
        int s = t*4 + j;
        keys[j] = g_selk[seg*SELCAP + s];
        vals[j] = g_selv[seg*SELCAP + s];
    }
    SegSortT(ts).Sort(keys, vals);
#pragma unroll
    for (int j = 0; j < 4; j++){
        int pos = t*4 + j;
        if (pos < kk) g_segsel[seg*SEGCAP + pos] = vals[j];
    }
}

__global__ void k_cand(const float* __restrict__ props, const float* __restrict__ obj){
    int idx = blockIdx.x*blockDim.x + threadIdx.x;
    if (idx >= NKC) return;
    int i = idx / KC, p = idx % KC;
    int l = lvl_of_p(p);
    int r = p - coff_of(l);
    int a = (int)g_segsel[(i*5 + l)*SEGCAP + r];
    int gi = i*ATOT + a;
    float o = obj[gi];
    float4 b = *(const float4*)(props + (size_t)gi*4);
    float x1 = fminf(fmaxf(b.x, 0.f), 512.f);
    float y1 = fminf(fmaxf(b.y, 0.f), 512.f);
    float x2 = fminf(fmaxf(b.z, 0.f), 512.f);
    float y2 = fminf(fmaxf(b.w, 0.f), 512.f);
    float sc = sigmoid_ref(o);
    float ws = __fsub_rn(x2, x1), hs = __fsub_rn(y2, y1);
    unsigned char v = (ws >= 0.001f) && (hs >= 0.001f) && (sc >= 0.0f);
    g_cbox[idx]  = make_float4(x1, y1, x2, y2);
    g_score[idx] = sc;
    g_valid[idx] = v;
    float mx = fmaxf(fmaxf(x1, y1), fmaxf(x2, y2));
    atomicMax(&g_imgmax[i], __float_as_uint(mx));
}

// Fused per-image: score keys + stable sort (ties -> p asc) + level-rank scan + pack.
__global__ void __launch_bounds__(1024) k_img(){
    int i = blockIdx.x, t = threadIdx.x;
    extern __shared__ char sm[];
    auto* S = reinterpret_cast<ImgSmemT*>(sm);

    unsigned keys[7], vals[7];
#pragma unroll
    for (int j = 0; j < 7; j++){
        int p = t*7 + j;
        if (p < KC){
            int idx = i*KC + p;
            float f = g_valid[idx] ? g_score[idx] : -INFINITY;
            keys[j] = ~fordera(f);              // descending score
        } else keys[j] = 0xFFFFFFFFu;           // sentinel (scores never NaN)
        vals[j] = (unsigned)p;
    }
    ImgSortT(S->u.sort).Sort(keys, vals);       // stable -> ties keep p ascending
    __syncthreads();

    unsigned long long items[7], ex[7];
    signed char lv[7];
#pragma unroll
    for (int j = 0; j < 7; j++){
        int q = t*7 + j;
        int p = (int)vals[j];
        if (q < KC && p < KC){
            int l = lvl_of_p(p);
            lv[j] = (signed char)l;
            items[j] = 1ull << (12*l);
        } else { lv[j] = -1; items[j] = 0ull; }
    }
    ImgScanT(S->u.scan).ExclusiveSum(items, ex);

    float mp1 = __fadd_rn(__uint_as_float(g_imgmax[i]), 1.0f);
#pragma unroll
    for (int j = 0; j < 7; j++){
        int q = t*7 + j;
        if (q >= KC || lv[j] < 0) continue;
        int p = (int)vals[j];
        g_v2b[i*KC + q] = (unsigned)p;
        int l = (int)lv[j];
        int r = (int)((ex[j] >> (12*l)) & 0xFFFull);
        int seg = i*5 + l;
        g_seglist[seg*SEGCAP + r] = (unsigned)q;
        if (r < segk_of(l)){
            int cand = i*KC + p;
            float4 b = g_cbox[cand];
            float off = __fmul_rn((float)l, mp1);
            float4 ob = make_float4(__fadd_rn(b.x, off), __fadd_rn(b.y, off),
                                    __fadd_rn(b.z, off), __fadd_rn(b.w, off));
            int u = seg*SEGCAP + r;
            g_segbox[u]  = ob;
            g_segarea[u] = __fmul_rn(__fsub_rn(ob.z, ob.x), __fsub_rn(ob.w, ob.y));
            if (!g_valid[cand])
                atomicOr(&g_seginval[seg*32 + (r >> 6)], 1ull << (r & 63));
        }
    }
}

// IoU mask v2 (unchanged from R11): overlap prescreen + exact test on survivors.
__global__ void __launch_bounds__(256) k_iou(){
    int seg = blockIdx.y;
    int m = segk_of(seg % 5);
    int wid  = threadIdx.x >> 5;
    int gw   = blockIdx.x*8 + wid;
    int lane = threadIdx.x & 31;
    int w = gw & 31;
    int rowBlk = gw >> 5;
    int row0 = rowBlk*128;
    if (row0 >= m) return;
    size_t base = (size_t)seg * SEGCAP;
    int j0 = w * 64;

    __shared__ float4 sB[8][64];
    __shared__ float  sAr[8][64];

    int rows[4];
#pragma unroll
    for (int k = 0; k < 4; k++) rows[k] = row0 + k*32 + lane;

    unsigned long long bits[4] = {0,0,0,0}, amb[4] = {0,0,0,0};

    if (j0 + 63 > row0){
        int jend = min(j0 + 64, m);
#pragma unroll
        for (int s = 0; s < 2; s++){
            int jj = lane + s*32;
            if (j0 + jj < m){
                sB[wid][jj]  = g_segbox[base + j0 + jj];
                sAr[wid][jj] = g_segarea[base + j0 + jj];
            }
        }
        __syncwarp();

        float4 A[4]; float aA[4];
#pragma unroll
        for (int k = 0; k < 4; k++){
            A[k]  = g_segbox[base + rows[k]];
            aA[k] = g_segarea[base + rows[k]];
        }

        unsigned long long xm[4] = {0,0,0,0};
        for (int j = j0; j < jend; j++){
            float4 B = sB[wid][j - j0];
            unsigned long long bm = 1ull << (j - j0);
#pragma unroll
            for (int k = 0; k < 4; k++){
                float ltx = fmaxf(A[k].x, B.x), lty = fmaxf(A[k].y, B.y);
                float rbx = fminf(A[k].z, B.z), rby = fminf(A[k].w, B.w);
                if (rbx > ltx && rby > lty) xm[k] |= bm;
            }
        }
#pragma unroll
        for (int k = 0; k < 4; k++){
            int cnt = rows[k] - j0 + 1;
            unsigned long long lowm = (cnt <= 0) ? 0ull :
                                      (cnt >= 64) ? ~0ull : ((1ull << cnt) - 1ull);
            xm[k] &= ~lowm;
        }
#pragma unroll
        for (int k = 0; k < 4; k++){
            unsigned long long x = xm[k];
            while (x){
                int b = __ffsll((long long)x) - 1;
                x &= x - 1ull;
                float4 B = sB[wid][b];
                float aB = sAr[wid][b];
                float ltx = fmaxf(A[k].x, B.x), lty = fmaxf(A[k].y, B.y);
                float rbx = fminf(A[k].z, B.z), rby = fminf(A[k].w, B.w);
                float ww = fmaxf(__fsub_rn(rbx, ltx), 0.f);
                float hh = fmaxf(__fsub_rn(rby, lty), 0.f);
                float inter = __fmul_rn(ww, hh);
                float s = __fadd_rn(aA[k], aB);
                float u = __fsub_rn(s, inter);
                float t = __fmaf_rn(0.7f, u, -inter);
                float tau = __fmul_rn(u, 2.384185791015625e-7f);
                unsigned long long bm = 1ull << b;
                if (t < -tau)        bits[k] |= bm;
                if (fabsf(t) <= tau) amb[k]  |= bm;
            }
        }
    }
#pragma unroll
    for (int k = 0; k < 4; k++){
        g_mask[(base + rows[k])*32 + w] = bits[k];
        unsigned long long am = amb[k];
        while (am){
            int b = __ffsll((long long)am) - 1;
            am &= am - 1ull;
            unsigned slot = atomicAdd(&g_ambcnt, 1u);
            if (slot < AMB_CAP)
                g_amb[slot] = ((unsigned)seg << 22) | ((unsigned)rows[k] << 11)
                            | (unsigned)(j0 + b);
        }
    }
}

// Serial greedy sweep (fix pass merged in: resolve ambiguous pairs first).
__global__ void k_sweep(){
    int seg = blockIdx.x, lane = threadIdx.x;
    int l = seg % 5, i = seg / 5, m = segk_of(l);
    size_t mb = (size_t)seg * SEGCAP * 32;
    size_t base = (size_t)seg * SEGCAP;

    unsigned n = g_ambcnt; if (n > AMB_CAP) n = AMB_CAP;
    for (unsigned u = lane; u < n; u += 32){
        unsigned e = g_amb[u];
        if ((int)(e >> 22) != seg) continue;
        int row = (int)((e >> 11) & 0x7FFu), j = (int)(e & 0x7FFu);
        float4 A = g_segbox[base + row]; float aA = g_segarea[base + row];
        float4 B = g_segbox[base + j];   float aB = g_segarea[base + j];
        float ltx = fmaxf(A.x, B.x), lty = fmaxf(A.y, B.y);
        float rbx = fminf(A.z, B.z), rby = fminf(A.w, B.w);
        float ww = fmaxf(__fsub_rn(rbx, ltx), 0.f);
        float hh = fmaxf(__fsub_rn(rby, lty), 0.f);
        float inter = __fmul_rn(ww, hh);
        float uu = __fsub_rn(__fadd_rn(aA, aB), inter);
        float tt = __fmaf_rn(0.7f, uu, -inter);
        float tau = __fmul_rn(uu, 2.384185791015625e-7f);
        bool guess = (tt < -tau);
        bool ex = exact_pred(inter, uu);
        if (ex != guess)
            atomicXor(&g_mask[(base + row)*32 + (j >> 6)], 1ull << (j & 63));
    }
    __syncwarp();
    __threadfence();

    unsigned long long removed = g_seginval[seg*32 + lane];
    unsigned long long buf[8];
#pragma unroll
    for (int k = 0; k < 8; k++)
        buf[k] = (k < m) ? g_mask[mb + (size_t)k*32 + lane] : 0ull;
    for (int basei = 0; basei < m; basei += 8){
        unsigned long long nbuf[8];
#pragma unroll
        for (int k = 0; k < 8; k++){
            int rr = basei + 8 + k;
            nbuf[k] = (rr < m) ? g_mask[mb + (size_t)rr*32 + lane] : 0ull;
        }
#pragma unroll
        for (int k = 0; k < 8; k++){
            int ii = basei + k;
            if (ii >= m) break;
            unsigned long long rw = __shfl_sync(0xFFFFFFFFu, removed, ii >> 6);
            if (!((rw >> (ii & 63)) & 1ull)) removed |= buf[k];
        }
#pragma unroll
        for (int k = 0; k < 8; k++) buf[k] = nbuf[k];
    }
    for (int b = 0; b < 64; b++){
        int r = lane*64 + b;
        if (r < m){
            unsigned q = g_seglist[seg*SEGCAP + r];
            g_keepq[i*KC + q] = (unsigned char)(((removed >> b) & 1ull) ^ 1ull);
        }
    }
}

__global__ void __launch_bounds__(512) k_out(float* __restrict__ out){
    int i = blockIdx.x, t = threadIdx.x;
    typedef cub::BlockScan<int, 512> BS;
    __shared__ typename BS::TempStorage ts;
    __shared__ int s_tot;
    int kp[14], ex[14];
#pragma unroll
    for (int j = 0; j < 14; j++){
        int q = t*14 + j;
        kp[j] = (q < KC) ? (int)g_keepq[i*KC + q] : 0;
    }
    int agg;
    BS(ts).ExclusiveSum(kp, ex, agg);
    if (t == 0) s_tot = agg;
    __syncthreads();
    float* ob = out + (size_t)i*POST*4;
    float* os = out + (size_t)NIMG*POST*4 + (size_t)i*POST;
#pragma unroll
    for (int j = 0; j < 14; j++){
        int q = t*14 + j;
        if (q < KC && kp[j] && ex[j] < POST){
            int p = (int)g_v2b[i*KC + q];
            int cand = i*KC + p;
            *(float4*)(ob + ex[j]*4) = g_cbox[cand];
            os[ex[j]] = g_score[cand];
        }
    }
    int T = min(s_tot, POST);
    for (int s = T + t; s < POST; s += 512){
        *(float4*)(ob + s*4) = make_float4(0.f, 0.f, 0.f, 0.f);
        os[s] = 0.f;
    }
}

// ---------------- launch ----------------
extern "C" void kernel_launch(void* const* d_in, const int* in_sizes, int n_in,
                              void* d_out, int out_size){
    const float* props = (const float*)d_in[0];
    const float* obj   = (const float*)d_in[1];
    float* out = (float*)d_out;

    cudaFuncSetAttribute(k_select, cudaFuncAttributeMaxDynamicSharedMemorySize,
                         NBIN*sizeof(unsigned));
    cudaFuncSetAttribute(k_segsort, cudaFuncAttributeMaxDynamicSharedMemorySize,
                         (int)sizeof(SegSortT::TempStorage));
    cudaFuncSetAttribute(k_img, cudaFuncAttributeMaxDynamicSharedMemorySize,
                         (int)sizeof(ImgSmemT));

    k_select <<<NSEG, 1024, NBIN*sizeof(unsigned)>>>(obj);
    k_segsort<<<NSEG, 1024, sizeof(SegSortT::TempStorage)>>>();
    k_cand   <<<(NKC + 255)/256, 256>>>(props, obj);
    k_img    <<<NIMG, 1024, sizeof(ImgSmemT)>>>();
    dim3 giou(64, NSEG);
    k_iou    <<<giou, 256>>>();
    k_sweep  <<<NSEG, 32>>>();
    k_out    <<<NIMG, 512>>>(out);
}

// round 13
// speedup vs baseline: 1.5731x; 1.1409x over previous
#include <cuda_runtime.h>
#include <cub/cub.cuh>
#include <cstdint>

#define NIMG 8
#define ATOT 65472
#define KC 6960
#define NSEG 40
#define SEGCAP 2048
#define SELCAP 4096
#define POST 2000
#define AMB_CAP 65536
#define NBIN 32768

// ---------------- static device scratch (no runtime allocation) ----------------
__device__ unsigned           g_segsel[NSEG*SEGCAP];     // sorted anchors (top-k order)
__device__ float4             g_cbox[NSEG*SEGCAP];       // clipped boxes, (seg,rank)
__device__ float              g_score[NSEG*SEGCAP];
__device__ unsigned           g_imgmax[NIMG];            // float bits (coords >= 0)
__device__ unsigned long long g_seginval[NSEG*32];
__device__ unsigned long long g_mask[(size_t)NSEG*SEGCAP*32];  // ~21 MB suppression bitmask
__device__ unsigned char      g_keepq[NSEG*SEGCAP];
__device__ unsigned           g_ambcnt;
__device__ unsigned           g_amb[AMB_CAP];

typedef cub::BlockRadixSort<unsigned, 1024, 4, unsigned> SegSortT;

// ---------------- helpers ----------------
__device__ __forceinline__ int lvl_of_p(int p){
    return (p<2000)?0:(p<4000)?1:(p<6000)?2:(p<6768)?3:4;
}
__device__ __forceinline__ int loff_of(int l){
    return (l==0)?0:(l==1)?49152:(l==2)?61440:(l==3)?64512:65280;
}
__device__ __forceinline__ int nlvl_of(int l){
    return (l==0)?49152:(l==1)?12288:(l==2)?3072:(l==3)?768:192;
}
__device__ __forceinline__ int coff_of(int l){
    return (l==0)?0:(l==1)?2000:(l==2)?4000:(l==3)?6000:6768;
}
__device__ __forceinline__ int segk_of(int l){
    return (l<3)?2000:(l==3)?768:192;
}
__device__ __forceinline__ unsigned fordera(float f){
    unsigned b = __float_as_uint(f);
    return (b & 0x80000000u) ? ~b : (b | 0x80000000u);
}

// XLA logistic: 0.5 + 0.5*tanh(0.5x), tanh = EmitFastTanh rational (Eigen coeffs).
__device__ __forceinline__ float sigmoid_ref(float x){
    float t  = __fmul_rn(0.5f, x);
    float r;
    if (fabsf(t) < 0.0004f) {
        r = t;
    } else {
        float tc = fmaxf(-9.0f, fminf(9.0f, t));
        float s  = __fmul_rn(tc, tc);
        float p  = __fmaf_rn(s, -2.76076847742355e-16f, 2.00018790482477e-13f);
        p = __fmaf_rn(p, s, -8.60467152213735e-11f);
        p = __fmaf_rn(p, s,  5.12229709037114e-08f);
        p = __fmaf_rn(p, s,  1.48572235717979e-05f);
        p = __fmaf_rn(p, s,  6.37261928875436e-04f);
        p = __fmaf_rn(p, s,  4.89352455891786e-03f);
        p = __fmul_rn(p, tc);
        float q = __fmaf_rn(s, 1.19825839466702e-06f, 1.18534705686654e-04f);
        q = __fmaf_rn(q, s, 2.26843463243900e-03f);
        q = __fmaf_rn(q, s, 4.89352518554385e-03f);
        r = __fdiv_rn(p, q);
    }
    return __fmaf_rn(0.5f, r, 0.5f);
}

// Exact predicate: RN(a/u) > 0.7f  <=>  a/u >= m,  m = 0.7f + 2^-25 = 23488103*2^-25.
__device__ __forceinline__ bool exact_pred(float a, float u){
    if (!(a > 0.f) || !(u > 0.f)) return false;
    unsigned ia = __float_as_uint(a), iu = __float_as_uint(u);
    int d = (int)(ia >> 23) - (int)(iu >> 23);
    if (d > 0)  return true;
    if (d < -1) return false;
    unsigned long long Ma = (ia & 0x7FFFFFu) | 0x800000u;
    unsigned long long Mu = (iu & 0x7FFFFFu) | 0x800000u;
    return (Ma << (d + 25)) >= 23488103ull * Mu;
}

// ---------------- kernels ----------------
// Fused per-segment select (histogram threshold) + stable compaction + in-block sort.
__global__ void __launch_bounds__(1024) k_sel2(const float* __restrict__ obj){
    int seg = blockIdx.x, i = seg/5, l = seg%5;
    int n = nlvl_of(l), kk = segk_of(l);
    int t = threadIdx.x;
    extern __shared__ unsigned char dsm[];
    unsigned* hist = (unsigned*)dsm;                 // [0, 128KB)
    unsigned* skey = (unsigned*)dsm;                 // [0, 16KB)  (after hist is dead)
    unsigned* sval = skey + SELCAP;                  // [16KB, 32KB)
    auto* sortTS = reinterpret_cast<SegSortT::TempStorage*>(dsm + 65536);
    typedef cub::BlockScan<int, 1024> BS;
    __shared__ typename BS::TempStorage ts;
    __shared__ int sB, sCnt;

    if (seg == 0){
        if (t < NIMG) g_imgmax[t] = 0u;
        if (t == 0)   g_ambcnt = 0u;
    }
    if (t < 32){                                     // padding ranks start invalid
        int r0 = t*64;
        unsigned long long v = (kk <= r0) ? ~0ull :
                               (kk >= r0+64) ? 0ull : (~0ull << (kk - r0));
        g_seginval[seg*32 + t] = v;
    }
    for (int b = t; b < NBIN; b += 1024) hist[b] = 0u;
    __syncthreads();

    const float* base = obj + (size_t)i*ATOT + loff_of(l);
    for (int s = t; s < n; s += 1024){
        unsigned d = ~fordera(base[s]);
        atomicAdd(&hist[d >> 17], 1u);
    }
    __syncthreads();

    {   // threshold bucket: first bucket where cumulative >= kk
        int b0 = t*32, s32 = 0;
        for (int j = 0; j < 32; j++) s32 += (int)hist[b0 + j];
        int ex;
        BS(ts).ExclusiveSum(s32, ex);
        if (ex < kk && kk <= ex + s32){
            int c = ex;
            for (int j = 0; j < 32; j++){
                c += (int)hist[b0 + j];
                if (c >= kk){ sB = b0 + j; sCnt = c; break; }
            }
        }
    }
    __syncthreads();
    int B = sB, cntAll = sCnt;

    // stable compaction into smem (thread-contiguous chunks preserve anchor order)
    int chunk = (n + 1023) / 1024;
    int lo = t*chunk, hi = min(n, lo + chunk);
    int cnt = 0;
    for (int s = lo; s < hi; s++){
        unsigned d = ~fordera(base[s]);
        if ((int)(d >> 17) <= B) cnt++;
    }
    int off;
    BS(ts).ExclusiveSum(cnt, off);
    for (int s = lo; s < hi; s++){
        unsigned d = ~fordera(base[s]);
        if ((int)(d >> 17) <= B){
            skey[off] = d;
            sval[off] = (unsigned)(loff_of(l) + s);  // absolute anchor
            off++;
        }
    }
    for (int s = cntAll + t; s < SELCAP; s += 1024) skey[s] = 0xFFFFFFFFu;
    __syncthreads();

    unsigned keys[4], vals[4];
#pragma unroll
    for (int j = 0; j < 4; j++){ keys[j] = skey[t*4 + j]; vals[j] = sval[t*4 + j]; }
    __syncthreads();
    SegSortT(*sortTS).Sort(keys, vals);              // stable -> ties keep anchor asc
#pragma unroll
    for (int j = 0; j < 4; j++){
        int pos = t*4 + j;
        if (pos < kk) g_segsel[seg*SEGCAP + pos] = vals[j];
    }
}

// Per-(seg,rank) candidate: clip, sigmoid, validity, image max.
__global__ void k_cand(const float* __restrict__ props, const float* __restrict__ obj){
    int idx = blockIdx.x*blockDim.x + threadIdx.x;
    if (idx >= NSEG*SEGCAP) return;
    int seg = idx >> 11, r = idx & 2047;
    int l = seg % 5, i = seg / 5;
    if (r >= segk_of(l)) return;
    int a  = (int)g_segsel[idx];
    int gi = i*ATOT + a;
    float o = obj[gi];
    float4 b = *(const float4*)(props + (size_t)gi*4);
    float x1 = fminf(fmaxf(b.x, 0.f), 512.f);
    float y1 = fminf(fmaxf(b.y, 0.f), 512.f);
    float x2 = fminf(fmaxf(b.z, 0.f), 512.f);
    float y2 = fminf(fmaxf(b.w, 0.f), 512.f);
    float sc = sigmoid_ref(o);
    float ws = __fsub_rn(x2, x1), hs = __fsub_rn(y2, y1);
    bool v = (ws >= 0.001f) && (hs >= 0.001f) && (sc >= 0.0f);
    g_cbox[idx]  = make_float4(x1, y1, x2, y2);
    g_score[idx] = sc;
    if (!v) atomicOr(&g_seginval[seg*32 + (r >> 6)], 1ull << (r & 63));
    float mx = fmaxf(fmaxf(x1, y1), fmaxf(x2, y2));
    atomicMax(&g_imgmax[i], __float_as_uint(mx));
}

// IoU mask: overlap prescreen + exact division-free test; offsets computed on the fly.
__global__ void __launch_bounds__(256) k_iou(){
    int seg = blockIdx.y;
    int l = seg % 5, i = seg / 5;
    int m = segk_of(l);
    int wid  = threadIdx.x >> 5;
    int gw   = blockIdx.x*8 + wid;
    int lane = threadIdx.x & 31;
    int w = gw & 31;
    int rowBlk = gw >> 5;
    int row0 = rowBlk*128;
    if (row0 >= m) return;
    size_t base = (size_t)seg * SEGCAP;
    int j0 = w * 64;

    __shared__ float4 sB[8][64];
    __shared__ float  sAr[8][64];

    float mp1 = __fadd_rn(__uint_as_float(g_imgmax[i]), 1.0f);
    float off = __fmul_rn((float)l, mp1);

    int rows[4];
#pragma unroll
    for (int k = 0; k < 4; k++) rows[k] = row0 + k*32 + lane;

    unsigned long long bits[4] = {0,0,0,0}, amb[4] = {0,0,0,0};

    if (j0 + 63 > row0){
        int jend = min(j0 + 64, m);
#pragma unroll
        for (int s = 0; s < 2; s++){
            int jj = lane + s*32;
            if (j0 + jj < m){
                float4 c = g_cbox[base + j0 + jj];
                float4 ob = make_float4(__fadd_rn(c.x, off), __fadd_rn(c.y, off),
                                        __fadd_rn(c.z, off), __fadd_rn(c.w, off));
                sB[wid][jj]  = ob;
                sAr[wid][jj] = __fmul_rn(__fsub_rn(ob.z, ob.x), __fsub_rn(ob.w, ob.y));
            }
        }
        __syncwarp();

        float4 A[4]; float aA[4];
#pragma unroll
        for (int k = 0; k < 4; k++){
            float4 c = g_cbox[base + rows[k]];
            A[k] = make_float4(__fadd_rn(c.x, off), __fadd_rn(c.y, off),
                               __fadd_rn(c.z, off), __fadd_rn(c.w, off));
            aA[k] = __fmul_rn(__fsub_rn(A[k].z, A[k].x), __fsub_rn(A[k].w, A[k].y));
        }

        unsigned long long xm[4] = {0,0,0,0};
        for (int j = j0; j < jend; j++){
            float4 B = sB[wid][j - j0];
            unsigned long long bm = 1ull << (j - j0);
#pragma unroll
            for (int k = 0; k < 4; k++){
                float ltx = fmaxf(A[k].x, B.x), lty = fmaxf(A[k].y, B.y);
                float rbx = fminf(A[k].z, B.z), rby = fminf(A[k].w, B.w);
                if (rbx > ltx && rby > lty) xm[k] |= bm;
            }
        }
#pragma unroll
        for (int k = 0; k < 4; k++){
            int cnt = rows[k] - j0 + 1;
            unsigned long long lowm = (cnt <= 0) ? 0ull :
                                      (cnt >= 64) ? ~0ull : ((1ull << cnt) - 1ull);
            xm[k] &= ~lowm;
        }
#pragma unroll
        for (int k = 0; k < 4; k++){
            unsigned long long x = xm[k];
            while (x){
                int b = __ffsll((long long)x) - 1;
                x &= x - 1ull;
                float4 B = sB[wid][b];
                float aB = sAr[wid][b];
                float ltx = fmaxf(A[k].x, B.x), lty = fmaxf(A[k].y, B.y);
                float rbx = fminf(A[k].z, B.z), rby = fminf(A[k].w, B.w);
                float ww = fmaxf(__fsub_rn(rbx, ltx), 0.f);
                float hh = fmaxf(__fsub_rn(rby, lty), 0.f);
                float inter = __fmul_rn(ww, hh);
                float s = __fadd_rn(aA[k], aB);
                float u = __fsub_rn(s, inter);
                float t = __fmaf_rn(0.7f, u, -inter);
                float tau = __fmul_rn(u, 2.384185791015625e-7f);
                unsigned long long bm = 1ull << b;
                if (t < -tau)        bits[k] |= bm;
                if (fabsf(t) <= tau) amb[k]  |= bm;
            }
        }
    }
#pragma unroll
    for (int k = 0; k < 4; k++){
        g_mask[(base + rows[k])*32 + w] = bits[k];
        unsigned long long am = amb[k];
        while (am){
            int b = __ffsll((long long)am) - 1;
            am &= am - 1ull;
            unsigned slot = atomicAdd(&g_ambcnt, 1u);
            if (slot < AMB_CAP)
                g_amb[slot] = ((unsigned)seg << 22) | ((unsigned)rows[k] << 11)
                            | (unsigned)(j0 + b);
        }
    }
}

// Serial greedy sweep; ambiguous pairs resolved exactly first. keep -> (seg,rank).
__global__ void k_sweep(){
    int seg = blockIdx.x, lane = threadIdx.x;
    int l = seg % 5, i = seg / 5, m = segk_of(l);
    size_t mb = (size_t)seg * SEGCAP * 32;
    size_t base = (size_t)seg * SEGCAP;
    float mp1 = __fadd_rn(__uint_as_float(g_imgmax[i]), 1.0f);
    float off = __fmul_rn((float)l, mp1);

    unsigned n = g_ambcnt; if (n > AMB_CAP) n = AMB_CAP;
    for (unsigned u = lane; u < n; u += 32){
        unsigned e = g_amb[u];
        if ((int)(e >> 22) != seg) continue;
        int row = (int)((e >> 11) & 0x7FFu), j = (int)(e & 0x7FFu);
        float4 ca = g_cbox[base + row];
        float4 A = make_float4(__fadd_rn(ca.x, off), __fadd_rn(ca.y, off),
                               __fadd_rn(ca.z, off), __fadd_rn(ca.w, off));
        float aA = __fmul_rn(__fsub_rn(A.z, A.x), __fsub_rn(A.w, A.y));
        float4 cb = g_cbox[base + j];
        float4 B = make_float4(__fadd_rn(cb.x, off), __fadd_rn(cb.y, off),
                               __fadd_rn(cb.z, off), __fadd_rn(cb.w, off));
        float aB = __fmul_rn(__fsub_rn(B.z, B.x), __fsub_rn(B.w, B.y));
        float ltx = fmaxf(A.x, B.x), lty = fmaxf(A.y, B.y);
        float rbx = fminf(A.z, B.z), rby = fminf(A.w, B.w);
        float ww = fmaxf(__fsub_rn(rbx, ltx), 0.f);
        float hh = fmaxf(__fsub_rn(rby, lty), 0.f);
        float inter = __fmul_rn(ww, hh);
        float uu = __fsub_rn(__fadd_rn(aA, aB), inter);
        float tt = __fmaf_rn(0.7f, uu, -inter);
        float tau = __fmul_rn(uu, 2.384185791015625e-7f);
        bool guess = (tt < -tau);
        bool ex = exact_pred(inter, uu);
        if (ex != guess)
            atomicXor(&g_mask[(base + row)*32 + (j >> 6)], 1ull << (j & 63));
    }
    __syncwarp();
    __threadfence();

    unsigned long long removed = g_seginval[seg*32 + lane];
    unsigned long long buf[8];
#pragma unroll
    for (int k = 0; k < 8; k++)
        buf[k] = (k < m) ? g_mask[mb + (size_t)k*32 + lane] : 0ull;
    for (int basei = 0; basei < m; basei += 8){
        unsigned long long nbuf[8];
#pragma unroll
        for (int k = 0; k < 8; k++){
            int rr = basei + 8 + k;
            nbuf[k] = (rr < m) ? g_mask[mb + (size_t)rr*32 + lane] : 0ull;
        }
#pragma unroll
        for (int k = 0; k < 8; k++){
            int ii = basei + k;
            if (ii >= m) break;
            unsigned long long rw = __shfl_sync(0xFFFFFFFFu, removed, ii >> 6);
            if (!((rw >> (ii & 63)) & 1ull)) removed |= buf[k];
        }
#pragma unroll
        for (int k = 0; k < 8; k++) buf[k] = nbuf[k];
    }
    for (int b = 0; b < 64; b++){
        int r = lane*64 + b;
        if (r < m)
            g_keepq[seg*SEGCAP + r] = (unsigned char)(((removed >> b) & 1ull) ^ 1ull);
    }
}

// Block-wide merge-path merge of two ascending u64 lists (unique keys).
__device__ void block_merge(const unsigned long long* A, int na,
                            const unsigned long long* B, int nb,
                            unsigned long long* out){
    int total = na + nb;
    int per = (total + 1023) / 1024;
    int d = threadIdx.x * per;
    if (d < total){
        int lo = max(0, d - nb), hi = min(d, na);
        while (lo < hi){
            int mid = (lo + hi) >> 1;
            if (A[mid] <= B[d - 1 - mid]) lo = mid + 1; else hi = mid;
        }
        int ia = lo, ib = d - lo;
        int end = min(d + per, total);
        for (int s = d; s < end; s++){
            bool ta = (ib >= nb) || (ia < na && A[ia] <= B[ib]);
            out[s] = ta ? A[ia++] : B[ib++];
        }
    }
    __syncthreads();
}

// Per-image: compact kept per segment (rank order = score order), 5-way merge, emit.
__global__ void __launch_bounds__(1024) k_out(float* __restrict__ out){
    int i = blockIdx.x, t = threadIdx.x;
    extern __shared__ unsigned long long sbuf[];
    unsigned long long* A  = sbuf;            // 7168: concat kept lists
    unsigned long long* Bf = sbuf + 7168;
    unsigned long long* Cf = sbuf + 14336;
    typedef cub::BlockScan<int, 1024> BS;
    __shared__ typename BS::TempStorage ts;

    int off[6]; off[0] = 0;
    int base = 0;
    for (int l = 0; l < 5; l++){
        int m = segk_of(l), seg = i*5 + l;
        int kp[2], ex[2], agg;
#pragma unroll
        for (int j = 0; j < 2; j++){
            int r = t*2 + j;
            kp[j] = (r < m) ? (int)g_keepq[seg*SEGCAP + r] : 0;
        }
        BS(ts).ExclusiveSum(kp, ex, agg);
#pragma unroll
        for (int j = 0; j < 2; j++){
            int r = t*2 + j;
            if (r < m && kp[j]){
                unsigned dk = ~fordera(g_score[seg*SEGCAP + r]);
                A[base + ex[j]] = ((unsigned long long)dk << 13)
                                | (unsigned long long)(coff_of(l) + r);
            }
        }
        base += agg;
        off[l+1] = base;
        __syncthreads();
    }
    int ntot = base;

    int n01 = off[2] - off[0], n23 = off[4] - off[2];
    block_merge(A + off[0], off[1]-off[0], A + off[1], off[2]-off[1], Cf);
    block_merge(A + off[2], off[3]-off[2], A + off[3], off[4]-off[3], Cf + n01);
    block_merge(Cf, n01, Cf + n01, n23, Bf);
    block_merge(Bf, off[4], A + off[4], ntot - off[4], Cf);

    float* ob = out + (size_t)i*POST*4;
    float* os = out + (size_t)NIMG*POST*4 + (size_t)i*POST;
    int T = min(ntot, POST);
    for (int s = t; s < POST; s += 1024){
        if (s < T){
            unsigned long long key = Cf[s];
            int p = (int)(key & 8191ull);
            int l = lvl_of_p(p), r = p - coff_of(l);
            int idx = (i*5 + l)*SEGCAP + r;
            *(float4*)(ob + s*4) = g_cbox[idx];
            os[s] = g_score[idx];
        } else {
            *(float4*)(ob + s*4) = make_float4(0.f, 0.f, 0.f, 0.f);
            os[s] = 0.f;
        }
    }
}

// ---------------- launch ----------------
extern "C" void kernel_launch(void* const* d_in, const int* in_sizes, int n_in,
                              void* d_out, int out_size){
    const float* props = (const float*)d_in[0];
    const float* obj   = (const float*)d_in[1];
    float* out = (float*)d_out;

    size_t dyn1 = NBIN*sizeof(unsigned);                      // 128 KB (hist; aliased)
    size_t need = 65536 + sizeof(SegSortT::TempStorage);
    if (need > dyn1) dyn1 = need;
    size_t dyn2 = 3u*7168u*sizeof(unsigned long long);        // 168 KB merge buffers

    cudaFuncSetAttribute(k_sel2, cudaFuncAttributeMaxDynamicSharedMemorySize, (int)dyn1);
    cudaFuncSetAttribute(k_out,  cudaFuncAttributeMaxDynamicSharedMemorySize, (int)dyn2);

    k_sel2 <<<NSEG, 1024, dyn1>>>(obj);
    k_cand <<<(NSEG*SEGCAP + 255)/256, 256>>>(props, obj);
    dim3 giou(64, NSEG);
    k_iou  <<<giou, 256>>>();
    k_sweep<<<NSEG, 32>>>();
    k_out  <<<NIMG, 1024, dyn2>>>(out);
}

// round 14
// speedup vs baseline: 2.0025x; 1.2729x over previous
#include <cuda_runtime.h>
#include <cub/cub.cuh>
#include <cstdint>

#define NIMG 8
#define ATOT 65472
#define KC 6960
#define NSEG 40
#define SEGCAP 2048
#define SELCAP 4096
#define POST 2000
#define AMB_CAP 65536
#define NBIN 32768

// ---------------- static device scratch (no runtime allocation) ----------------
__device__ unsigned           g_segsel[NSEG*SEGCAP];     // sorted anchors (top-k order)
__device__ float4             g_cbox[NSEG*SEGCAP];       // clipped boxes, (seg,rank)
__device__ float              g_score[NSEG*SEGCAP];
__device__ unsigned           g_imgmax[NIMG];            // float bits (coords >= 0)
__device__ unsigned long long g_seginval[NSEG*32];
__device__ unsigned long long g_mask[(size_t)NSEG*SEGCAP*32];  // ~21 MB suppression bitmask
__device__ unsigned char      g_keepq[NSEG*SEGCAP];
__device__ unsigned           g_ambcnt;
__device__ unsigned           g_amb[AMB_CAP];

typedef cub::BlockRadixSort<unsigned, 1024, 4, unsigned> SegSortT;

// ---------------- helpers ----------------
__device__ __forceinline__ int lvl_of_p(int p){
    return (p<2000)?0:(p<4000)?1:(p<6000)?2:(p<6768)?3:4;
}
__device__ __forceinline__ int loff_of(int l){
    return (l==0)?0:(l==1)?49152:(l==2)?61440:(l==3)?64512:65280;
}
__device__ __forceinline__ int nlvl_of(int l){
    return (l==0)?49152:(l==1)?12288:(l==2)?3072:(l==3)?768:192;
}
__device__ __forceinline__ int coff_of(int l){
    return (l==0)?0:(l==1)?2000:(l==2)?4000:(l==3)?6000:6768;
}
__device__ __forceinline__ int segk_of(int l){
    return (l<3)?2000:(l==3)?768:192;
}
__device__ __forceinline__ unsigned fordera(float f){
    unsigned b = __float_as_uint(f);
    return (b & 0x80000000u) ? ~b : (b | 0x80000000u);
}

// XLA logistic: 0.5 + 0.5*tanh(0.5x), tanh = EmitFastTanh rational (Eigen coeffs).
__device__ __forceinline__ float sigmoid_ref(float x){
    float t  = __fmul_rn(0.5f, x);
    float r;
    if (fabsf(t) < 0.0004f) {
        r = t;
    } else {
        float tc = fmaxf(-9.0f, fminf(9.0f, t));
        float s  = __fmul_rn(tc, tc);
        float p  = __fmaf_rn(s, -2.76076847742355e-16f, 2.00018790482477e-13f);
        p = __fmaf_rn(p, s, -8.60467152213735e-11f);
        p = __fmaf_rn(p, s,  5.12229709037114e-08f);
        p = __fmaf_rn(p, s,  1.48572235717979e-05f);
        p = __fmaf_rn(p, s,  6.37261928875436e-04f);
        p = __fmaf_rn(p, s,  4.89352455891786e-03f);
        p = __fmul_rn(p, tc);
        float q = __fmaf_rn(s, 1.19825839466702e-06f, 1.18534705686654e-04f);
        q = __fmaf_rn(q, s, 2.26843463243900e-03f);
        q = __fmaf_rn(q, s, 4.89352518554385e-03f);
        r = __fdiv_rn(p, q);
    }
    return __fmaf_rn(0.5f, r, 0.5f);
}

// Exact predicate: RN(a/u) > 0.7f  <=>  a/u >= m,  m = 0.7f + 2^-25 = 23488103*2^-25.
__device__ __forceinline__ bool exact_pred(float a, float u){
    if (!(a > 0.f) || !(u > 0.f)) return false;
    unsigned ia = __float_as_uint(a), iu = __float_as_uint(u);
    int d = (int)(ia >> 23) - (int)(iu >> 23);
    if (d > 0)  return true;
    if (d < -1) return false;
    unsigned long long Ma = (ia & 0x7FFFFFu) | 0x800000u;
    unsigned long long Mu = (iu & 0x7FFFFFu) | 0x800000u;
    return (Ma << (d + 25)) >= 23488103ull * Mu;
}

// ---------------- kernels ----------------
// Fused per-segment select (histogram threshold) + stable compaction + in-block sort.
__global__ void __launch_bounds__(1024) k_sel2(const float* __restrict__ obj){
    int seg = blockIdx.x, i = seg/5, l = seg%5;
    int n = nlvl_of(l), kk = segk_of(l);
    int t = threadIdx.x;
    extern __shared__ unsigned char dsm[];
    unsigned* hist = (unsigned*)dsm;                 // [0, 128KB)
    unsigned* skey = (unsigned*)dsm;                 // [0, 16KB)  (after hist is dead)
    unsigned* sval = skey + SELCAP;                  // [16KB, 32KB)
    auto* sortTS = reinterpret_cast<SegSortT::TempStorage*>(dsm + 65536);
    typedef cub::BlockScan<int, 1024> BS;
    __shared__ typename BS::TempStorage ts;
    __shared__ int sB, sCnt;

    if (seg == 0){
        if (t < NIMG) g_imgmax[t] = 0u;
        if (t == 0)   g_ambcnt = 0u;
    }
    if (t < 32){                                     // padding ranks start invalid
        int r0 = t*64;
        unsigned long long v = (kk <= r0) ? ~0ull :
                               (kk >= r0+64) ? 0ull : (~0ull << (kk - r0));
        g_seginval[seg*32 + t] = v;
    }
    for (int b = t; b < NBIN; b += 1024) hist[b] = 0u;
    __syncthreads();

    const float* base = obj + (size_t)i*ATOT + loff_of(l);
    for (int s = t; s < n; s += 1024){
        unsigned d = ~fordera(base[s]);
        atomicAdd(&hist[d >> 17], 1u);
    }
    __syncthreads();

    {   // threshold bucket: first bucket where cumulative >= kk
        int b0 = t*32, s32 = 0;
        for (int j = 0; j < 32; j++) s32 += (int)hist[b0 + j];
        int ex;
        BS(ts).ExclusiveSum(s32, ex);
        if (ex < kk && kk <= ex + s32){
            int c = ex;
            for (int j = 0; j < 32; j++){
                c += (int)hist[b0 + j];
                if (c >= kk){ sB = b0 + j; sCnt = c; break; }
            }
        }
    }
    __syncthreads();
    int B = sB, cntAll = sCnt;

    // stable compaction into smem (thread-contiguous chunks preserve anchor order)
    int chunk = (n + 1023) / 1024;
    int lo = t*chunk, hi = min(n, lo + chunk);
    int cnt = 0;
    for (int s = lo; s < hi; s++){
        unsigned d = ~fordera(base[s]);
        if ((int)(d >> 17) <= B) cnt++;
    }
    int off;
    BS(ts).ExclusiveSum(cnt, off);
    for (int s = lo; s < hi; s++){
        unsigned d = ~fordera(base[s]);
        if ((int)(d >> 17) <= B){
            skey[off] = d;
            sval[off] = (unsigned)(loff_of(l) + s);  // absolute anchor
            off++;
        }
    }
    for (int s = cntAll + t; s < SELCAP; s += 1024) skey[s] = 0xFFFFFFFFu;
    __syncthreads();

    unsigned keys[4], vals[4];
#pragma unroll
    for (int j = 0; j < 4; j++){ keys[j] = skey[t*4 + j]; vals[j] = sval[t*4 + j]; }
    __syncthreads();
    SegSortT(*sortTS).Sort(keys, vals);              // stable -> ties keep anchor asc
#pragma unroll
    for (int j = 0; j < 4; j++){
        int pos = t*4 + j;
        if (pos < kk) g_segsel[seg*SEGCAP + pos] = vals[j];
    }
}

// Per-(seg,rank) candidate: clip, sigmoid, validity, image max.
__global__ void k_cand(const float* __restrict__ props, const float* __restrict__ obj){
    int idx = blockIdx.x*blockDim.x + threadIdx.x;
    if (idx >= NSEG*SEGCAP) return;
    int seg = idx >> 11, r = idx & 2047;
    int l = seg % 5, i = seg / 5;
    if (r >= segk_of(l)) return;
    int a  = (int)g_segsel[idx];
    int gi = i*ATOT + a;
    float o = obj[gi];
    float4 b = *(const float4*)(props + (size_t)gi*4);
    float x1 = fminf(fmaxf(b.x, 0.f), 512.f);
    float y1 = fminf(fmaxf(b.y, 0.f), 512.f);
    float x2 = fminf(fmaxf(b.z, 0.f), 512.f);
    float y2 = fminf(fmaxf(b.w, 0.f), 512.f);
    float sc = sigmoid_ref(o);
    float ws = __fsub_rn(x2, x1), hs = __fsub_rn(y2, y1);
    bool v = (ws >= 0.001f) && (hs >= 0.001f) && (sc >= 0.0f);
    g_cbox[idx]  = make_float4(x1, y1, x2, y2);
    g_score[idx] = sc;
    if (!v) atomicOr(&g_seginval[seg*32 + (r >> 6)], 1ull << (r & 63));
    float mx = fmaxf(fmaxf(x1, y1), fmaxf(x2, y2));
    atomicMax(&g_imgmax[i], __float_as_uint(mx));
}

// IoU mask: overlap prescreen + exact division-free test; offsets computed on the fly.
__global__ void __launch_bounds__(256) k_iou(){
    int seg = blockIdx.y;
    int l = seg % 5, i = seg / 5;
    int m = segk_of(l);
    int wid  = threadIdx.x >> 5;
    int gw   = blockIdx.x*8 + wid;
    int lane = threadIdx.x & 31;
    int w = gw & 31;
    int rowBlk = gw >> 5;
    int row0 = rowBlk*128;
    if (row0 >= m) return;
    size_t base = (size_t)seg * SEGCAP;
    int j0 = w * 64;

    __shared__ float4 sB[8][64];
    __shared__ float  sAr[8][64];

    float mp1 = __fadd_rn(__uint_as_float(g_imgmax[i]), 1.0f);
    float off = __fmul_rn((float)l, mp1);

    int rows[4];
#pragma unroll
    for (int k = 0; k < 4; k++) rows[k] = row0 + k*32 + lane;

    unsigned long long bits[4] = {0,0,0,0}, amb[4] = {0,0,0,0};

    if (j0 + 63 > row0){
        int jend = min(j0 + 64, m);
#pragma unroll
        for (int s = 0; s < 2; s++){
            int jj = lane + s*32;
            if (j0 + jj < m){
                float4 c = g_cbox[base + j0 + jj];
                float4 ob = make_float4(__fadd_rn(c.x, off), __fadd_rn(c.y, off),
                                        __fadd_rn(c.z, off), __fadd_rn(c.w, off));
                sB[wid][jj]  = ob;
                sAr[wid][jj] = __fmul_rn(__fsub_rn(ob.z, ob.x), __fsub_rn(ob.w, ob.y));
            }
        }
        __syncwarp();

        float4 A[4]; float aA[4];
#pragma unroll
        for (int k = 0; k < 4; k++){
            float4 c = g_cbox[base + rows[k]];
            A[k] = make_float4(__fadd_rn(c.x, off), __fadd_rn(c.y, off),
                               __fadd_rn(c.z, off), __fadd_rn(c.w, off));
            aA[k] = __fmul_rn(__fsub_rn(A[k].z, A[k].x), __fsub_rn(A[k].w, A[k].y));
        }

        unsigned long long xm[4] = {0,0,0,0};
        for (int j = j0; j < jend; j++){
            float4 B = sB[wid][j - j0];
            unsigned long long bm = 1ull << (j - j0);
#pragma unroll
            for (int k = 0; k < 4; k++){
                float ltx = fmaxf(A[k].x, B.x), lty = fmaxf(A[k].y, B.y);
                float rbx = fminf(A[k].z, B.z), rby = fminf(A[k].w, B.w);
                if (rbx > ltx && rby > lty) xm[k] |= bm;
            }
        }
#pragma unroll
        for (int k = 0; k < 4; k++){
            int cnt = rows[k] - j0 + 1;
            unsigned long long lowm = (cnt <= 0) ? 0ull :
                                      (cnt >= 64) ? ~0ull : ((1ull << cnt) - 1ull);
            xm[k] &= ~lowm;
        }
#pragma unroll
        for (int k = 0; k < 4; k++){
            unsigned long long x = xm[k];
            while (x){
                int b = __ffsll((long long)x) - 1;
                x &= x - 1ull;
                float4 B = sB[wid][b];
                float aB = sAr[wid][b];
                float ltx = fmaxf(A[k].x, B.x), lty = fmaxf(A[k].y, B.y);
                float rbx = fminf(A[k].z, B.z), rby = fminf(A[k].w, B.w);
                float ww = fmaxf(__fsub_rn(rbx, ltx), 0.f);
                float hh = fmaxf(__fsub_rn(rby, lty), 0.f);
                float inter = __fmul_rn(ww, hh);
                float s = __fadd_rn(aA[k], aB);
                float u = __fsub_rn(s, inter);
                float t = __fmaf_rn(0.7f, u, -inter);
                float tau = __fmul_rn(u, 2.384185791015625e-7f);
                unsigned long long bm = 1ull << b;
                if (t < -tau)        bits[k] |= bm;
                if (fabsf(t) <= tau) amb[k]  |= bm;
            }
        }
    }
#pragma unroll
    for (int k = 0; k < 4; k++){
        g_mask[(base + rows[k])*32 + w] = bits[k];
        unsigned long long am = amb[k];
        while (am){
            int b = __ffsll((long long)am) - 1;
            am &= am - 1ull;
            unsigned slot = atomicAdd(&g_ambcnt, 1u);
            if (slot < AMB_CAP)
                g_amb[slot] = ((unsigned)seg << 22) | ((unsigned)rows[k] << 11)
                            | (unsigned)(j0 + b);
        }
    }
}

// Word-block serial sweep: cp.async-staged 64-row blocks, owner-lane intra-word
// resolve (pure ALU), one shfl per 64 rows, branch-free suppression ORs.
// Fixpoint identical to the per-row greedy sweep.
__global__ void __launch_bounds__(32, 1) k_sweep(){
    int seg = blockIdx.x, lane = threadIdx.x;
    int l = seg % 5, i = seg / 5, m = segk_of(l);
    int nblk = (m + 63) >> 6;
    size_t base = (size_t)seg * SEGCAP;
    float mp1 = __fadd_rn(__uint_as_float(g_imgmax[i]), 1.0f);
    float off = __fmul_rn((float)l, mp1);

    // resolve ambiguous pairs exactly (this segment only) before reading mask
    unsigned n = g_ambcnt; if (n > AMB_CAP) n = AMB_CAP;
    for (unsigned u = lane; u < n; u += 32){
        unsigned e = g_amb[u];
        if ((int)(e >> 22) != seg) continue;
        int row = (int)((e >> 11) & 0x7FFu), j = (int)(e & 0x7FFu);
        float4 ca = g_cbox[base + row];
        float4 A = make_float4(__fadd_rn(ca.x, off), __fadd_rn(ca.y, off),
                               __fadd_rn(ca.z, off), __fadd_rn(ca.w, off));
        float aA = __fmul_rn(__fsub_rn(A.z, A.x), __fsub_rn(A.w, A.y));
        float4 cb = g_cbox[base + j];
        float4 B = make_float4(__fadd_rn(cb.x, off), __fadd_rn(cb.y, off),
                               __fadd_rn(cb.z, off), __fadd_rn(cb.w, off));
        float aB = __fmul_rn(__fsub_rn(B.z, B.x), __fsub_rn(B.w, B.y));
        float ltx = fmaxf(A.x, B.x), lty = fmaxf(A.y, B.y);
        float rbx = fminf(A.z, B.z), rby = fminf(A.w, B.w);
        float ww = fmaxf(__fsub_rn(rbx, ltx), 0.f);
        float hh = fmaxf(__fsub_rn(rby, lty), 0.f);
        float inter = __fmul_rn(ww, hh);
        float uu = __fsub_rn(__fadd_rn(aA, aB), inter);
        float tt = __fmaf_rn(0.7f, uu, -inter);
        float tau = __fmul_rn(uu, 2.384185791015625e-7f);
        bool guess = (tt < -tau);
        bool ex = exact_pred(inter, uu);
        if (ex != guess)
            atomicXor(&g_mask[(base + row)*32 + (j >> 6)], 1ull << (j & 63));
    }
    __syncwarp();
    __threadfence();

    __shared__ __align__(16) unsigned long long smb[3][64*32];  // 3 x 16KB ring
    const char* gsrc = (const char*)&g_mask[base*32];

    // issue one 64-row block (16KB) into ring slot b
    auto issue_blk = [&](int W, int b){
        unsigned dst = (unsigned)__cvta_generic_to_shared(&smb[b][0]) + lane*16;
        const char* src = gsrc + (size_t)W*16384 + lane*16;
#pragma unroll
        for (int c = 0; c < 32; c++){
            asm volatile("cp.async.cg.shared.global [%0], [%1], 16;"
                         :: "r"(dst + c*512), "l"(src + c*512));
        }
        asm volatile("cp.async.commit_group;" ::: "memory");
    };

    unsigned long long removed = g_seginval[seg*32 + lane];

    issue_blk(0, 0);
    if (nblk > 1) issue_blk(1, 1);

    for (int W = 0; W < nblk; W++){
        if (W + 1 < nblk) asm volatile("cp.async.wait_group 1;" ::: "memory");
        else              asm volatile("cp.async.wait_group 0;" ::: "memory");
        __syncwarp();

        const unsigned long long* sb = smb[W % 3];
        unsigned long long col[64];
#pragma unroll
        for (int j = 0; j < 64; j++) col[j] = sb[j*32 + lane];

        if (W + 2 < nblk) issue_blk(W + 2, (W + 2) % 3);

        // owner-lane (lane == W) intra-word resolve; other lanes compute garbage
        unsigned long long rm = removed;
#pragma unroll
        for (int j = 0; j < 64; j++)
            if (!((rm >> j) & 1ull)) rm |= col[j];
        unsigned long long kw = ~__shfl_sync(0xFFFFFFFFu, rm, W);   // alive bits

        // branch-free suppression accumulation from alive rows
        if (kw){
#pragma unroll
            for (int j = 0; j < 64; j++)
                removed |= col[j] & (unsigned long long)(-(long long)((kw >> j) & 1ull));
        }
    }

    for (int b = 0; b < 64; b++){
        int r = lane*64 + b;
        if (r < m)
            g_keepq[seg*SEGCAP + r] = (unsigned char)(((removed >> b) & 1ull) ^ 1ull);
    }
}

// Block-wide merge-path merge of two ascending u64 lists (unique keys).
__device__ void block_merge(const unsigned long long* A, int na,
                            const unsigned long long* B, int nb,
                            unsigned long long* out){
    int total = na + nb;
    int per = (total + 1023) / 1024;
    int d = threadIdx.x * per;
    if (d < total){
        int lo = max(0, d - nb), hi = min(d, na);
        while (lo < hi){
            int mid = (lo + hi) >> 1;
            if (A[mid] <= B[d - 1 - mid]) lo = mid + 1; else hi = mid;
        }
        int ia = lo, ib = d - lo;
        int end = min(d + per, total);
        for (int s = d; s < end; s++){
            bool ta = (ib >= nb) || (ia < na && A[ia] <= B[ib]);
            out[s] = ta ? A[ia++] : B[ib++];
        }
    }
    __syncthreads();
}

// Per-image: compact kept per segment (rank order = score order), 5-way merge, emit.
__global__ void __launch_bounds__(1024) k_out(float* __restrict__ out){
    int i = blockIdx.x, t = threadIdx.x;
    extern __shared__ unsigned long long sbuf[];
    unsigned long long* A  = sbuf;            // 7168: concat kept lists
    unsigned long long* Bf = sbuf + 7168;
    unsigned long long* Cf = sbuf + 14336;
    typedef cub::BlockScan<int, 1024> BS;
    __shared__ typename BS::TempStorage ts;

    int off[6]; off[0] = 0;
    int base = 0;
    for (int l = 0; l < 5; l++){
        int m = segk_of(l), seg = i*5 + l;
        int kp[2], ex[2], agg;
#pragma unroll
        for (int j = 0; j < 2; j++){
            int r = t*2 + j;
            kp[j] = (r < m) ? (int)g_keepq[seg*SEGCAP + r] : 0;
        }
        BS(ts).ExclusiveSum(kp, ex, agg);
#pragma unroll
        for (int j = 0; j < 2; j++){
            int r = t*2 + j;
            if (r < m && kp[j]){
                unsigned dk = ~fordera(g_score[seg*SEGCAP + r]);
                A[base + ex[j]] = ((unsigned long long)dk << 13)
                                | (unsigned long long)(coff_of(l) + r);
            }
        }
        base += agg;
        off[l+1] = base;
        __syncthreads();
    }
    int ntot = base;

    int n01 = off[2] - off[0], n23 = off[4] - off[2];
    block_merge(A + off[0], off[1]-off[0], A + off[1], off[2]-off[1], Cf);
    block_merge(A + off[2], off[3]-off[2], A + off[3], off[4]-off[3], Cf + n01);
    block_merge(Cf, n01, Cf + n01, n23, Bf);
    block_merge(Bf, off[4], A + off[4], ntot - off[4], Cf);

    float* ob = out + (size_t)i*POST*4;
    float* os = out + (size_t)NIMG*POST*4 + (size_t)i*POST;
    int T = min(ntot, POST);
    for (int s = t; s < POST; s += 1024){
        if (s < T){
            unsigned long long key = Cf[s];
            int p = (int)(key & 8191ull);
            int l = lvl_of_p(p), r = p - coff_of(l);
            int idx = (i*5 + l)*SEGCAP + r;
            *(float4*)(ob + s*4) = g_cbox[idx];
            os[s] = g_score[idx];
        } else {
            *(float4*)(ob + s*4) = make_float4(0.f, 0.f, 0.f, 0.f);
            os[s] = 0.f;
        }
    }
}

// ---------------- launch ----------------
extern "C" void kernel_launch(void* const* d_in, const int* in_sizes, int n_in,
                              void* d_out, int out_size){
    const float* props = (const float*)d_in[0];
    const float* obj   = (const float*)d_in[1];
    float* out = (float*)d_out;

    size_t dyn1 = NBIN*sizeof(unsigned);                      // 128 KB (hist; aliased)
    size_t need = 65536 + sizeof(SegSortT::TempStorage);
    if (need > dyn1) dyn1 = need;
    size_t dyn2 = 3u*7168u*sizeof(unsigned long long);        // 168 KB merge buffers

    cudaFuncSetAttribute(k_sel2, cudaFuncAttributeMaxDynamicSharedMemorySize, (int)dyn1);
    cudaFuncSetAttribute(k_out,  cudaFuncAttributeMaxDynamicSharedMemorySize, (int)dyn2);

    k_sel2 <<<NSEG, 1024, dyn1>>>(obj);
    k_cand <<<(NSEG*SEGCAP + 255)/256, 256>>>(props, obj);
    dim3 giou(64, NSEG);
    k_iou  <<<giou, 256>>>();
    k_sweep<<<NSEG, 32>>>();
    k_out  <<<NIMG, 1024, dyn2>>>(out);
}

// round 15
// speedup vs baseline: 2.6710x; 1.3338x over previous
#include <cuda_runtime.h>
#include <cub/cub.cuh>
#include <cstdint>

#define NIMG 8
#define ATOT 65472
#define KC 6960
#define NSEG 40
#define SEGCAP 2048
#define SELCAP 4096
#define POST 2000
#define AMB_CAP 65536
#define NBIN 4096

// ---------------- static device scratch (no runtime allocation) ----------------
__device__ float4             g_cbox[NSEG*SEGCAP];       // clipped boxes, (seg,rank)
__device__ float              g_score[NSEG*SEGCAP];
__device__ unsigned           g_segmax[NSEG];            // float bits of per-seg coord max
__device__ unsigned long long g_seginval[NSEG*32];
__device__ unsigned long long g_mask[(size_t)NSEG*SEGCAP*32];  // ~21 MB suppression bitmask
__device__ unsigned char      g_keepq[NSEG*SEGCAP];
__device__ unsigned           g_ambcnt;
__device__ unsigned           g_amb[AMB_CAP];

typedef cub::BlockRadixSort<unsigned long long, 1024, 4> SelSortT;

// ---------------- helpers ----------------
__device__ __forceinline__ int lvl_of_p(int p){
    return (p<2000)?0:(p<4000)?1:(p<6000)?2:(p<6768)?3:4;
}
__device__ __forceinline__ int loff_of(int l){
    return (l==0)?0:(l==1)?49152:(l==2)?61440:(l==3)?64512:65280;
}
__device__ __forceinline__ int nlvl_of(int l){
    return (l==0)?49152:(l==1)?12288:(l==2)?3072:(l==3)?768:192;
}
__device__ __forceinline__ int coff_of(int l){
    return (l==0)?0:(l==1)?2000:(l==2)?4000:(l==3)?6000:6768;
}
__device__ __forceinline__ int segk_of(int l){
    return (l<3)?2000:(l==3)?768:192;
}
__device__ __forceinline__ unsigned fordera(float f){
    unsigned b = __float_as_uint(f);
    return (b & 0x80000000u) ? ~b : (b | 0x80000000u);
}
// image coordinate max from per-segment maxes (exact max, order-free)
__device__ __forceinline__ float img_mp1(int i){
    float mx =            __uint_as_float(g_segmax[i*5+0]);
    mx = fmaxf(mx, __uint_as_float(g_segmax[i*5+1]));
    mx = fmaxf(mx, __uint_as_float(g_segmax[i*5+2]));
    mx = fmaxf(mx, __uint_as_float(g_segmax[i*5+3]));
    mx = fmaxf(mx, __uint_as_float(g_segmax[i*5+4]));
    return __fadd_rn(mx, 1.0f);
}

// XLA logistic: 0.5 + 0.5*tanh(0.5x), tanh = EmitFastTanh rational (Eigen coeffs).
__device__ __forceinline__ float sigmoid_ref(float x){
    float t  = __fmul_rn(0.5f, x);
    float r;
    if (fabsf(t) < 0.0004f) {
        r = t;
    } else {
        float tc = fmaxf(-9.0f, fminf(9.0f, t));
        float s  = __fmul_rn(tc, tc);
        float p  = __fmaf_rn(s, -2.76076847742355e-16f, 2.00018790482477e-13f);
        p = __fmaf_rn(p, s, -8.60467152213735e-11f);
        p = __fmaf_rn(p, s,  5.12229709037114e-08f);
        p = __fmaf_rn(p, s,  1.48572235717979e-05f);
        p = __fmaf_rn(p, s,  6.37261928875436e-04f);
        p = __fmaf_rn(p, s,  4.89352455891786e-03f);
        p = __fmul_rn(p, tc);
        float q = __fmaf_rn(s, 1.19825839466702e-06f, 1.18534705686654e-04f);
        q = __fmaf_rn(q, s, 2.26843463243900e-03f);
        q = __fmaf_rn(q, s, 4.89352518554385e-03f);
        r = __fdiv_rn(p, q);
    }
    return __fmaf_rn(0.5f, r, 0.5f);
}

// Exact predicate: RN(a/u) > 0.7f  <=>  a/u >= m,  m = 0.7f + 2^-25 = 23488103*2^-25.
__device__ __forceinline__ bool exact_pred(float a, float u){
    if (!(a > 0.f) || !(u > 0.f)) return false;
    unsigned ia = __float_as_uint(a), iu = __float_as_uint(u);
    int d = (int)(ia >> 23) - (int)(iu >> 23);
    if (d > 0)  return true;
    if (d < -1) return false;
    unsigned long long Ma = (ia & 0x7FFFFFu) | 0x800000u;
    unsigned long long Mu = (iu & 0x7FFFFFu) | 0x800000u;
    return (Ma << (d + 25)) >= 23488103ull * Mu;
}

// ---------------- kernels ----------------
// Fused per-segment: histogram threshold select + atomic compaction (48-bit
// composite key canonicalizes order) + in-block sort + candidate build.
__global__ void __launch_bounds__(1024) k_sel2(const float* __restrict__ obj,
                                               const float* __restrict__ props){
    int seg = blockIdx.x, i = seg/5, l = seg%5;
    int n = nlvl_of(l), kk = segk_of(l);
    int t = threadIdx.x;
    extern __shared__ unsigned char dsm[];
    unsigned* hist = (unsigned*)dsm;                          // 16KB
    unsigned long long* skey = (unsigned long long*)dsm;      // 32KB (aliases hist)
    auto* sortTS = reinterpret_cast<SelSortT::TempStorage*>(dsm + 32768);
    typedef cub::BlockScan<int, 1024> BS;
    __shared__ typename BS::TempStorage ts;
    __shared__ int sB;
    __shared__ unsigned sCnt, sMax;

    if (seg == 0 && t == 0) g_ambcnt = 0u;
    if (t == 0){ sCnt = 0u; sMax = 0u; }
    if (t < 32){                                     // padding ranks start invalid
        int r0 = t*64;
        unsigned long long v = (kk <= r0) ? ~0ull :
                               (kk >= r0+64) ? 0ull : (~0ull << (kk - r0));
        g_seginval[seg*32 + t] = v;
    }
    for (int b = t; b < NBIN; b += 1024) hist[b] = 0u;
    __syncthreads();

    const float* base = obj + (size_t)i*ATOT + loff_of(l);
    for (int s = t; s < n; s += 1024){
        unsigned d = ~fordera(base[s]);
        atomicAdd(&hist[d >> 20], 1u);
    }
    __syncthreads();

    {   // threshold bucket: first bucket where cumulative >= kk
        int b0 = t*4, s4 = 0;
#pragma unroll
        for (int j = 0; j < 4; j++) s4 += (int)hist[b0 + j];
        int ex;
        BS(ts).ExclusiveSum(s4, ex);
        if (ex < kk && kk <= ex + s4){
            int c = ex;
#pragma unroll
            for (int j = 0; j < 4; j++){
                c += (int)hist[b0 + j];
                if (c >= kk){ sB = b0 + j; break; }
            }
        }
    }
    __syncthreads();
    int B = sB;

    // single-pass unordered compaction; composite key restores canonical order
    for (int s = t; s < n; s += 1024){
        unsigned d = ~fordera(base[s]);
        if ((int)(d >> 20) <= B){
            unsigned pos = atomicAdd(&sCnt, 1u);
            if (pos < SELCAP)
                skey[pos] = ((unsigned long long)d << 16) | (unsigned long long)s;
        }
    }
    __syncthreads();
    unsigned cntAll = sCnt; if (cntAll > SELCAP) cntAll = SELCAP;
    for (int s = (int)cntAll + t; s < SELCAP; s += 1024) skey[s] = ~0ull;
    __syncthreads();

    unsigned long long keys[4];
#pragma unroll
    for (int j = 0; j < 4; j++) keys[j] = skey[t*4 + j];
    __syncthreads();
    SelSortT(*sortTS).Sort(keys, 0, 48);             // (desckey asc, anchor asc)

    // fused candidate build
    size_t sbase = (size_t)seg * SEGCAP;
    float lmax = 0.f;
#pragma unroll
    for (int j = 0; j < 4; j++){
        int pos = t*4 + j;
        if (pos < kk){
            unsigned long long key = keys[j];
            int s = (int)(key & 0xFFFFull);
            unsigned d = (unsigned)(key >> 16);
            unsigned f = ~d;                         // fordera bits
            unsigned ob = (f & 0x80000000u) ? (f & 0x7FFFFFFFu) : ~f;
            float o = __uint_as_float(ob);
            int gi = i*ATOT + loff_of(l) + s;
            float4 b = *(const float4*)(props + (size_t)gi*4);
            float x1 = fminf(fmaxf(b.x, 0.f), 512.f);
            float y1 = fminf(fmaxf(b.y, 0.f), 512.f);
            float x2 = fminf(fmaxf(b.z, 0.f), 512.f);
            float y2 = fminf(fmaxf(b.w, 0.f), 512.f);
            float sc = sigmoid_ref(o);
            float ws = __fsub_rn(x2, x1), hs = __fsub_rn(y2, y1);
            bool v = (ws >= 0.001f) && (hs >= 0.001f) && (sc >= 0.0f);
            g_cbox[sbase + pos]  = make_float4(x1, y1, x2, y2);
            g_score[sbase + pos] = sc;
            if (!v) atomicOr(&g_seginval[seg*32 + (pos >> 6)], 1ull << (pos & 63));
            lmax = fmaxf(lmax, fmaxf(fmaxf(x1, y1), fmaxf(x2, y2)));
        }
    }
    atomicMax(&sMax, __float_as_uint(lmax));         // coords >= 0: uint max == fp max
    __syncthreads();
    if (t == 0) g_segmax[seg] = sMax;
}

// IoU mask: overlap prescreen + exact division-free test; offsets computed on the fly.
__global__ void __launch_bounds__(256) k_iou(){
    int seg = blockIdx.y;
    int l = seg % 5, i = seg / 5;
    int m = segk_of(l);
    int wid  = threadIdx.x >> 5;
    int gw   = blockIdx.x*8 + wid;
    int lane = threadIdx.x & 31;
    int w = gw & 31;
    int rowBlk = gw >> 5;
    int row0 = rowBlk*128;
    if (row0 >= m) return;
    size_t base = (size_t)seg * SEGCAP;
    int j0 = w * 64;

    __shared__ float4 sB[8][64];
    __shared__ float  sAr[8][64];

    float off = __fmul_rn((float)l, img_mp1(i));

    int rows[4];
#pragma unroll
    for (int k = 0; k < 4; k++) rows[k] = row0 + k*32 + lane;

    unsigned long long bits[4] = {0,0,0,0}, amb[4] = {0,0,0,0};

    if (j0 + 63 > row0){
        int jend = min(j0 + 64, m);
#pragma unroll
        for (int s = 0; s < 2; s++){
            int jj = lane + s*32;
            if (j0 + jj < m){
                float4 c = g_cbox[base + j0 + jj];
                float4 ob = make_float4(__fadd_rn(c.x, off), __fadd_rn(c.y, off),
                                        __fadd_rn(c.z, off), __fadd_rn(c.w, off));
                sB[wid][jj]  = ob;
                sAr[wid][jj] = __fmul_rn(__fsub_rn(ob.z, ob.x), __fsub_rn(ob.w, ob.y));
            }
        }
        __syncwarp();

        float4 A[4]; float aA[4];
#pragma unroll
        for (int k = 0; k < 4; k++){
            float4 c = g_cbox[base + rows[k]];
            A[k] = make_float4(__fadd_rn(c.x, off), __fadd_rn(c.y, off),
                               __fadd_rn(c.z, off), __fadd_rn(c.w, off));
            aA[k] = __fmul_rn(__fsub_rn(A[k].z, A[k].x), __fsub_rn(A[k].w, A[k].y));
        }

        unsigned long long xm[4] = {0,0,0,0};
        for (int j = j0; j < jend; j++){
            float4 B = sB[wid][j - j0];
            unsigned long long bm = 1ull << (j - j0);
#pragma unroll
            for (int k = 0; k < 4; k++){
                float ltx = fmaxf(A[k].x, B.x), lty = fmaxf(A[k].y, B.y);
                float rbx = fminf(A[k].z, B.z), rby = fminf(A[k].w, B.w);
                if (rbx > ltx && rby > lty) xm[k] |= bm;
            }
        }
#pragma unroll
        for (int k = 0; k < 4; k++){
            int cnt = rows[k] - j0 + 1;
            unsigned long long lowm = (cnt <= 0) ? 0ull :
                                      (cnt >= 64) ? ~0ull : ((1ull << cnt) - 1ull);
            xm[k] &= ~lowm;
        }
#pragma unroll
        for (int k = 0; k < 4; k++){
            unsigned long long x = xm[k];
            while (x){
                int b = __ffsll((long long)x) - 1;
                x &= x - 1ull;
                float4 B = sB[wid][b];
                float aB = sAr[wid][b];
                float ltx = fmaxf(A[k].x, B.x), lty = fmaxf(A[k].y, B.y);
                float rbx = fminf(A[k].z, B.z), rby = fminf(A[k].w, B.w);
                float ww = fmaxf(__fsub_rn(rbx, ltx), 0.f);
                float hh = fmaxf(__fsub_rn(rby, lty), 0.f);
                float inter = __fmul_rn(ww, hh);
                float s = __fadd_rn(aA[k], aB);
                float u = __fsub_rn(s, inter);
                float t = __fmaf_rn(0.7f, u, -inter);
                float tau = __fmul_rn(u, 2.384185791015625e-7f);
                unsigned long long bm = 1ull << b;
                if (t < -tau)        bits[k] |= bm;
                if (fabsf(t) <= tau) amb[k]  |= bm;
            }
        }
    }
#pragma unroll
    for (int k = 0; k < 4; k++){
        g_mask[(base + rows[k])*32 + w] = bits[k];
        unsigned long long am = amb[k];
        while (am){
            int b = __ffsll((long long)am) - 1;
            am &= am - 1ull;
            unsigned slot = atomicAdd(&g_ambcnt, 1u);
            if (slot < AMB_CAP)
                g_amb[slot] = ((unsigned)seg << 22) | ((unsigned)rows[k] << 11)
                            | (unsigned)(j0 + b);
        }
    }
}

// Word-block serial sweep: cp.async-staged 64-row blocks, owner-lane intra-word
// resolve (pure ALU), one shfl per 64 rows, branch-free suppression ORs.
__global__ void __launch_bounds__(32, 1) k_sweep(){
    int seg = blockIdx.x, lane = threadIdx.x;
    int l = seg % 5, i = seg / 5, m = segk_of(l);
    int nblk = (m + 63) >> 6;
    size_t base = (size_t)seg * SEGCAP;
    float off = __fmul_rn((float)l, img_mp1(i));

    // resolve ambiguous pairs exactly (this segment only) before reading mask
    unsigned n = g_ambcnt; if (n > AMB_CAP) n = AMB_CAP;
    for (unsigned u = lane; u < n; u += 32){
        unsigned e = g_amb[u];
        if ((int)(e >> 22) != seg) continue;
        int row = (int)((e >> 11) & 0x7FFu), j = (int)(e & 0x7FFu);
        float4 ca = g_cbox[base + row];
        float4 A = make_float4(__fadd_rn(ca.x, off), __fadd_rn(ca.y, off),
                               __fadd_rn(ca.z, off), __fadd_rn(ca.w, off));
        float aA = __fmul_rn(__fsub_rn(A.z, A.x), __fsub_rn(A.w, A.y));
        float4 cb = g_cbox[base + j];
        float4 B = make_float4(__fadd_rn(cb.x, off), __fadd_rn(cb.y, off),
                               __fadd_rn(cb.z, off), __fadd_rn(cb.w, off));
        float aB = __fmul_rn(__fsub_rn(B.z, B.x), __fsub_rn(B.w, B.y));
        float ltx = fmaxf(A.x, B.x), lty = fmaxf(A.y, B.y);
        float rbx = fminf(A.z, B.z), rby = fminf(A.w, B.w);
        float ww = fmaxf(__fsub_rn(rbx, ltx), 0.f);
        float hh = fmaxf(__fsub_rn(rby, lty), 0.f);
        float inter = __fmul_rn(ww, hh);
        float uu = __fsub_rn(__fadd_rn(aA, aB), inter);
        float tt = __fmaf_rn(0.7f, uu, -inter);
        float tau = __fmul_rn(uu, 2.384185791015625e-7f);
        bool guess = (tt < -tau);
        bool ex = exact_pred(inter, uu);
        if (ex != guess)
            atomicXor(&g_mask[(base + row)*32 + (j >> 6)], 1ull << (j & 63));
    }
    __syncwarp();
    __threadfence();

    __shared__ __align__(16) unsigned long long smb[3][64*32];  // 3 x 16KB ring
    const char* gsrc = (const char*)&g_mask[base*32];

    auto issue_blk = [&](int W, int b){
        unsigned dst = (unsigned)__cvta_generic_to_shared(&smb[b][0]) + lane*16;
        const char* src = gsrc + (size_t)W*16384 + lane*16;
#pragma unroll
        for (int c = 0; c < 32; c++){
            asm volatile("cp.async.cg.shared.global [%0], [%1], 16;"
                         :: "r"(dst + c*512), "l"(src + c*512));
        }
        asm volatile("cp.async.commit_group;" ::: "memory");
    };

    unsigned long long removed = g_seginval[seg*32 + lane];

    issue_blk(0, 0);
    if (nblk > 1) issue_blk(1, 1);

    for (int W = 0; W < nblk; W++){
        if (W + 1 < nblk) asm volatile("cp.async.wait_group 1;" ::: "memory");
        else              asm volatile("cp.async.wait_group 0;" ::: "memory");
        __syncwarp();

        const unsigned long long* sb = smb[W % 3];
        unsigned long long col[64];
#pragma unroll
        for (int j = 0; j < 64; j++) col[j] = sb[j*32 + lane];

        if (W + 2 < nblk) issue_blk(W + 2, (W + 2) % 3);

        unsigned long long rm = removed;
#pragma unroll
        for (int j = 0; j < 64; j++)
            if (!((rm >> j) & 1ull)) rm |= col[j];
        unsigned long long kw = ~__shfl_sync(0xFFFFFFFFu, rm, W);   // alive bits

        if (kw){
#pragma unroll
            for (int j = 0; j < 64; j++)
                removed |= col[j] & (unsigned long long)(-(long long)((kw >> j) & 1ull));
        }
    }

    for (int b = 0; b < 64; b++){
        int r = lane*64 + b;
        if (r < m)
            g_keepq[seg*SEGCAP + r] = (unsigned char)(((removed >> b) & 1ull) ^ 1ull);
    }
}

// Block-wide merge-path merge of two ascending u64 lists (unique keys).
__device__ void block_merge(const unsigned long long* A, int na,
                            const unsigned long long* B, int nb,
                            unsigned long long* out){
    int total = na + nb;
    int per = (total + 1023) / 1024;
    int d = threadIdx.x * per;
    if (d < total){
        int lo = max(0, d - nb), hi = min(d, na);
        while (lo < hi){
            int mid = (lo + hi) >> 1;
            if (A[mid] <= B[d - 1 - mid]) lo = mid + 1; else hi = mid;
        }
        int ia = lo, ib = d - lo;
        int end = min(d + per, total);
        for (int s = d; s < end; s++){
            bool ta = (ib >= nb) || (ia < na && A[ia] <= B[ib]);
            out[s] = ta ? A[ia++] : B[ib++];
        }
    }
    __syncthreads();
}

// Per-image: compact kept per segment (rank order = score order), 5-way merge, emit.
__global__ void __launch_bounds__(1024) k_out(float* __restrict__ out){
    int i = blockIdx.x, t = threadIdx.x;
    extern __shared__ unsigned long long sbuf[];
    unsigned long long* A  = sbuf;            // 7168: concat kept lists
    unsigned long long* Bf = sbuf + 7168;
    unsigned long long* Cf = sbuf + 14336;
    typedef cub::BlockScan<int, 1024> BS;
    __shared__ typename BS::TempStorage ts;

    int off[6]; off[0] = 0;
    int base = 0;
    for (int l = 0; l < 5; l++){
        int m = segk_of(l), seg = i*5 + l;
        int kp[2], ex[2], agg;
#pragma unroll
        for (int j = 0; j < 2; j++){
            int r = t*2 + j;
            kp[j] = (r < m) ? (int)g_keepq[seg*SEGCAP + r] : 0;
        }
        BS(ts).ExclusiveSum(kp, ex, agg);
#pragma unroll
        for (int j = 0; j < 2; j++){
            int r = t*2 + j;
            if (r < m && kp[j]){
                unsigned dk = ~fordera(g_score[seg*SEGCAP + r]);
                A[base + ex[j]] = ((unsigned long long)dk << 13)
                                | (unsigned long long)(coff_of(l) + r);
            }
        }
        base += agg;
        off[l+1] = base;
        __syncthreads();
    }
    int ntot = base;

    int n01 = off[2] - off[0], n23 = off[4] - off[2];
    block_merge(A + off[0], off[1]-off[0], A + off[1], off[2]-off[1], Cf);
    block_merge(A + off[2], off[3]-off[2], A + off[3], off[4]-off[3], Cf + n01);
    block_merge(Cf, n01, Cf + n01, n23, Bf);
    block_merge(Bf, off[4], A + off[4], ntot - off[4], Cf);

    float* ob = out + (size_t)i*POST*4;
    float* os = out + (size_t)NIMG*POST*4 + (size_t)i*POST;
    int T = min(ntot, POST);
    for (int s = t; s < POST; s += 1024){
        if (s < T){
            unsigned long long key = Cf[s];
            int p = (int)(key & 8191ull);
            int l = lvl_of_p(p), r = p - coff_of(l);
            int idx = (i*5 + l)*SEGCAP + r;
            *(float4*)(ob + s*4) = g_cbox[idx];
            os[s] = g_score[idx];
        } else {
            *(float4*)(ob + s*4) = make_float4(0.f, 0.f, 0.f, 0.f);
            os[s] = 0.f;
        }
    }
}

// ---------------- launch ----------------
extern "C" void kernel_launch(void* const* d_in, const int* in_sizes, int n_in,
                              void* d_out, int out_size){
    const float* props = (const float*)d_in[0];
    const float* obj   = (const float*)d_in[1];
    float* out = (float*)d_out;

    size_t dyn1 = 32768 + sizeof(SelSortT::TempStorage);
    size_t dyn2 = 3u*7168u*sizeof(unsigned long long);        // 168 KB merge buffers

    cudaFuncSetAttribute(k_sel2, cudaFuncAttributeMaxDynamicSharedMemorySize, (int)dyn1);
    cudaFuncSetAttribute(k_out,  cudaFuncAttributeMaxDynamicSharedMemorySize, (int)dyn2);

    k_sel2 <<<NSEG, 1024, dyn1>>>(obj, props);
    dim3 giou(64, NSEG);
    k_iou  <<<giou, 256>>>();
    k_sweep<<<NSEG, 32>>>();
    k_out  <<<NIMG, 1024, dyn2>>>(out);
}